// round 1
// baseline (speedup 1.0000x reference)
#include <cuda_runtime.h>
#include <cstdint>

// ---------------- scratch (no cudaMalloc allowed) ----------------
// qkv: [4096][2304] fp32 = 37.7MB ; ao: [4096][768] fp32 = 12.6MB
__device__ float g_qkv[4096 * 2304];
__device__ float g_ao[4096 * 768];

// ---------------- GEMM: C[M,N] = A[M,K] @ B[N,K]^T + bias[N] ----------------
// BM=BN=128, BK=16, 256 threads, 8x8 microtile, float4 everywhere.
// Requires: M%128==0, N%128==0, K%16==0 (holds: M=4096, N in {2304,768}, K=768)
#define GBM 128
#define GBN 128
#define GBK 16

__global__ __launch_bounds__(256, 2)
void gemm_nt(const float* __restrict__ A, const float* __restrict__ B,
             const float* __restrict__ bias, float* __restrict__ C,
             int M, int N, int K) {
    __shared__ float As[GBK][GBM + 4];  // k-major, padded
    __shared__ float Bs[GBK][GBN + 4];

    const int tid = threadIdx.x;
    const int tx = tid & 15;        // n dim
    const int ty = tid >> 4;        // m dim
    const int mBase = blockIdx.y * GBM;
    const int nBase = blockIdx.x * GBN;

    float acc[8][8] = {};

    for (int k0 = 0; k0 < K; k0 += GBK) {
        // load 128 rows x 16 k of A and B (512 float4 each, 2 per thread)
#pragma unroll
        for (int i = 0; i < 2; i++) {
            int lin = tid + i * 256;
            int row = lin >> 2;
            int fq  = lin & 3;
            float4 av = *(const float4*)(A + (size_t)(mBase + row) * K + k0 + fq * 4);
            As[fq * 4 + 0][row] = av.x;
            As[fq * 4 + 1][row] = av.y;
            As[fq * 4 + 2][row] = av.z;
            As[fq * 4 + 3][row] = av.w;
            float4 bv = *(const float4*)(B + (size_t)(nBase + row) * K + k0 + fq * 4);
            Bs[fq * 4 + 0][row] = bv.x;
            Bs[fq * 4 + 1][row] = bv.y;
            Bs[fq * 4 + 2][row] = bv.z;
            Bs[fq * 4 + 3][row] = bv.w;
        }
        __syncthreads();

#pragma unroll
        for (int k = 0; k < GBK; k++) {
            float a[8], b[8];
            *(float4*)&a[0] = *(const float4*)&As[k][ty * 8];
            *(float4*)&a[4] = *(const float4*)&As[k][ty * 8 + 4];
            *(float4*)&b[0] = *(const float4*)&Bs[k][tx * 8];
            *(float4*)&b[4] = *(const float4*)&Bs[k][tx * 8 + 4];
#pragma unroll
            for (int i = 0; i < 8; i++)
#pragma unroll
                for (int j = 0; j < 8; j++)
                    acc[i][j] += a[i] * b[j];
        }
        __syncthreads();
    }

    // epilogue
    float bj[8];
#pragma unroll
    for (int j = 0; j < 8; j++) bj[j] = bias[nBase + tx * 8 + j];

#pragma unroll
    for (int i = 0; i < 8; i++) {
        int row = mBase + ty * 8 + i;
        float4 v0, v1;
        v0.x = acc[i][0] + bj[0]; v0.y = acc[i][1] + bj[1];
        v0.z = acc[i][2] + bj[2]; v0.w = acc[i][3] + bj[3];
        v1.x = acc[i][4] + bj[4]; v1.y = acc[i][5] + bj[5];
        v1.z = acc[i][6] + bj[6]; v1.w = acc[i][7] + bj[7];
        float* cp = C + (size_t)row * N + nBase + tx * 8;
        *(float4*)cp       = v0;
        *(float4*)(cp + 4) = v1;
    }
}

// ---------------- Flash attention ----------------
// Per block: one (b,h) and a 64-query tile. Online softmax over 32 key tiles of 64.
// 256 threads: rg = tid>>4 (16 row groups of 4), cg = tid&15; cols strided: cg + 16*cc.
#define AT_PAD 68  // row pitch (floats) for 64-wide tiles; keeps float4 alignment

__global__ __launch_bounds__(256)
void attn_kernel(const float* __restrict__ qkv, float* __restrict__ ao) {
    extern __shared__ float sm[];
    float* Qs = sm;                    // [64][AT_PAD]
    float* Ks = Qs + 64 * AT_PAD;      // [64][AT_PAD]
    float* Vs = Ks + 64 * AT_PAD;      // [64][AT_PAD]
    float* Ss = Vs + 64 * AT_PAD;      // [64][AT_PAD]

    const int tid = threadIdx.x;
    const int bh = blockIdx.y;
    const int b = bh / 12;
    const int h = bh % 12;
    const int q0 = blockIdx.x * 64;
    const int rg = tid >> 4;
    const int cg = tid & 15;
    const size_t RS = 2304;  // qkv row stride

    const float* qbase = qkv + ((size_t)b * 2048 + q0) * RS + h * 64;

    // load Q tile [64][64]
#pragma unroll
    for (int i = 0; i < 4; i++) {
        int lin = tid + i * 256;
        int r = lin >> 4;
        int f = lin & 15;
        float4 v = *(const float4*)(qbase + (size_t)r * RS + f * 4);
        *(float4*)(Qs + r * AT_PAD + f * 4) = v;
    }

    float o[4][4] = {};
    float mrow[4], lrow[4];
#pragma unroll
    for (int rr = 0; rr < 4; rr++) { mrow[rr] = -1e30f; lrow[rr] = 0.f; }

    const float scale = 0.125f;  // 1/sqrt(64)

    for (int kt = 0; kt < 32; kt++) {
        const int k0 = kt * 64;
        const float* kbase = qkv + ((size_t)b * 2048 + k0) * RS + 768 + h * 64;
        const float* vbase = qkv + ((size_t)b * 2048 + k0) * RS + 1536 + h * 64;

        __syncthreads();  // previous iter's Ks/Vs/Ss reads done
#pragma unroll
        for (int i = 0; i < 4; i++) {
            int lin = tid + i * 256;
            int r = lin >> 4;
            int f = lin & 15;
            *(float4*)(Ks + r * AT_PAD + f * 4) =
                *(const float4*)(kbase + (size_t)r * RS + f * 4);
            *(float4*)(Vs + r * AT_PAD + f * 4) =
                *(const float4*)(vbase + (size_t)r * RS + f * 4);
        }
        __syncthreads();

        // S = Q @ K^T (4 rows x 4 strided cols per thread)
        float s[4][4] = {};
#pragma unroll
        for (int d = 0; d < 64; d += 4) {
            float4 q4[4], k4[4];
#pragma unroll
            for (int rr = 0; rr < 4; rr++)
                q4[rr] = *(const float4*)(Qs + (rg * 4 + rr) * AT_PAD + d);
#pragma unroll
            for (int cc = 0; cc < 4; cc++)
                k4[cc] = *(const float4*)(Ks + (cg + 16 * cc) * AT_PAD + d);
#pragma unroll
            for (int rr = 0; rr < 4; rr++)
#pragma unroll
                for (int cc = 0; cc < 4; cc++)
                    s[rr][cc] += q4[rr].x * k4[cc].x + q4[rr].y * k4[cc].y +
                                 q4[rr].z * k4[cc].z + q4[rr].w * k4[cc].w;
        }

        // online softmax per row; 16 threads (cg) share each row
#pragma unroll
        for (int rr = 0; rr < 4; rr++) {
            float t0 = s[rr][0] * scale, t1 = s[rr][1] * scale;
            float t2 = s[rr][2] * scale, t3 = s[rr][3] * scale;
            float mloc = fmaxf(fmaxf(t0, t1), fmaxf(t2, t3));
#pragma unroll
            for (int off = 8; off >= 1; off >>= 1)
                mloc = fmaxf(mloc, __shfl_xor_sync(0xffffffffu, mloc, off, 16));
            float mnew = fmaxf(mrow[rr], mloc);
            float alpha = __expf(mrow[rr] - mnew);
            mrow[rr] = mnew;

            float p0 = __expf(t0 - mnew), p1 = __expf(t1 - mnew);
            float p2 = __expf(t2 - mnew), p3 = __expf(t3 - mnew);
            float* srow = Ss + (rg * 4 + rr) * AT_PAD + cg;
            srow[0]  = p0;
            srow[16] = p1;
            srow[32] = p2;
            srow[48] = p3;
            float lloc = (p0 + p1) + (p2 + p3);
#pragma unroll
            for (int off = 8; off >= 1; off >>= 1)
                lloc += __shfl_xor_sync(0xffffffffu, lloc, off, 16);
            lrow[rr] = lrow[rr] * alpha + lloc;
#pragma unroll
            for (int cc = 0; cc < 4; cc++) o[rr][cc] *= alpha;
        }
        __syncthreads();  // Ss fully written

        // O += P @ V
#pragma unroll
        for (int j = 0; j < 64; j += 4) {
            float p4[4][4];
#pragma unroll
            for (int rr = 0; rr < 4; rr++)
                *(float4*)p4[rr] = *(const float4*)(Ss + (rg * 4 + rr) * AT_PAD + j);
#pragma unroll
            for (int jj = 0; jj < 4; jj++) {
                float vv[4];
#pragma unroll
                for (int cc = 0; cc < 4; cc++)
                    vv[cc] = Vs[(j + jj) * AT_PAD + cg + 16 * cc];
#pragma unroll
                for (int rr = 0; rr < 4; rr++)
#pragma unroll
                    for (int cc = 0; cc < 4; cc++)
                        o[rr][cc] += p4[rr][jj] * vv[cc];
            }
        }
    }

    // write out: ao[b][n][h*64 + d]
#pragma unroll
    for (int rr = 0; rr < 4; rr++) {
        float inv = 1.0f / lrow[rr];
        int row = q0 + rg * 4 + rr;
        float* obase = ao + ((size_t)b * 2048 + row) * 768 + h * 64 + cg;
#pragma unroll
        for (int cc = 0; cc < 4; cc++)
            obase[16 * cc] = o[rr][cc] * inv;
    }
}

// ---------------- launch ----------------
extern "C" void kernel_launch(void* const* d_in, const int* in_sizes, int n_in,
                              void* d_out, int out_size) {
    const float* x      = (const float*)d_in[0];
    const float* qkv_w  = (const float*)d_in[1];
    const float* qkv_b  = (const float*)d_in[2];
    const float* proj_w = (const float*)d_in[3];
    const float* proj_b = (const float*)d_in[4];
    float* out = (float*)d_out;

    float* qkv = nullptr;
    float* ao  = nullptr;
    cudaGetSymbolAddress((void**)&qkv, g_qkv);
    cudaGetSymbolAddress((void**)&ao,  g_ao);

    // 1) qkv = x @ qkv_w^T + qkv_b : [4096,2304]
    gemm_nt<<<dim3(2304 / GBN, 4096 / GBM), 256>>>(x, qkv_w, qkv_b, qkv,
                                                   4096, 2304, 768);

    // 2) attention -> ao [4096,768]
    const int attn_smem = 4 * 64 * AT_PAD * (int)sizeof(float);  // 69632 B
    cudaFuncSetAttribute(attn_kernel,
                         cudaFuncAttributeMaxDynamicSharedMemorySize, attn_smem);
    attn_kernel<<<dim3(32, 24), 256, attn_smem>>>(qkv, ao);

    // 3) out = ao @ proj_w^T + proj_b : [4096,768]
    gemm_nt<<<dim3(768 / GBN, 4096 / GBM), 256>>>(ao, proj_w, proj_b, out,
                                                  4096, 768, 768);
}

// round 5
// speedup vs baseline: 1.5646x; 1.5646x over previous
#include <cuda_runtime.h>
#include <cuda_bf16.h>
#include <cstdint>

// ---------------- scratch (no cudaMalloc allowed) ----------------
__device__ float g_qkv[4096 * 2304];                 // fp32 qkv
__device__ float g_ao [4096 * 768];                  // fp32 attention out
__device__ __nv_bfloat16 g_A2[4096 * 2304];          // activations split-concat [M][3K] = [hi|lo|hi]
__device__ __nv_bfloat16 g_B1[2304 * 2304];          // qkv_w split-concat [hi|hi|lo]
__device__ __nv_bfloat16 g_B2[768 * 2304];           // proj_w split-concat [hi|hi|lo]

// ================= helpers =================
__device__ __forceinline__ uint32_t smem_u32(const void* p) {
    uint32_t a;
    asm("{ .reg .u64 t; cvta.to.shared.u64 t, %1; cvt.u32.u64 %0, t; }" : "=r"(a) : "l"(p));
    return a;
}
__device__ __forceinline__ void ldsm4(uint32_t* r, uint32_t a) {
    asm volatile("ldmatrix.sync.aligned.m8n8.x4.shared.b16 {%0,%1,%2,%3}, [%4];"
                 : "=r"(r[0]), "=r"(r[1]), "=r"(r[2]), "=r"(r[3]) : "r"(a));
}
__device__ __forceinline__ void ldsm4t(uint32_t* r, uint32_t a) {
    asm volatile("ldmatrix.sync.aligned.m8n8.x4.trans.shared.b16 {%0,%1,%2,%3}, [%4];"
                 : "=r"(r[0]), "=r"(r[1]), "=r"(r[2]), "=r"(r[3]) : "r"(a));
}
__device__ __forceinline__ void mma16816(float* d, const uint32_t* a, uint32_t b0, uint32_t b1) {
    asm volatile("mma.sync.aligned.m16n8k16.row.col.f32.bf16.bf16.f32 "
                 "{%0,%1,%2,%3},{%4,%5,%6,%7},{%8,%9},{%0,%1,%2,%3};"
                 : "+f"(d[0]), "+f"(d[1]), "+f"(d[2]), "+f"(d[3])
                 : "r"(a[0]), "r"(a[1]), "r"(a[2]), "r"(a[3]), "r"(b0), "r"(b1));
}
__device__ __forceinline__ void cp16(uint32_t saddr, const void* gaddr) {
    asm volatile("cp.async.cg.shared.global [%0], [%1], 16;" :: "r"(saddr), "l"(gaddr));
}
__device__ __forceinline__ void cp_commit() { asm volatile("cp.async.commit_group;" ::: "memory"); }
__device__ __forceinline__ void cp_wait1()  { asm volatile("cp.async.wait_group 1;" ::: "memory"); }

__device__ __forceinline__ void split2(float x, float y, __nv_bfloat162& hi, __nv_bfloat162& lo) {
    __nv_bfloat16 hx = __float2bfloat16(x), hy = __float2bfloat16(y);
    hi.x = hx; hi.y = hy;
    lo.x = __float2bfloat16(x - __bfloat162float(hx));
    lo.y = __float2bfloat16(y - __bfloat162float(hy));
}

// ===== split-concat: in[R][K] f32 -> out[R][3K] bf16 =====
// loMid=1: [hi|lo|hi]  (activations / A operand)
// loMid=0: [hi|hi|lo]  (weights / B operand)
// Pairing gives A'.B' = Ah.Bh + Al.Bh + Ah.Bl  (drops only Al.Bl ~1e-5 rel)
__global__ void split3(const float* __restrict__ in, __nv_bfloat16* __restrict__ out,
                       int R, int K, int loMid) {
    int i = blockIdx.x * blockDim.x + threadIdx.x;
    int per_row = K >> 2;
    if (i >= R * per_row) return;
    int r = i / per_row, f = i % per_row;
    float4 v = *(const float4*)(in + (size_t)r * K + f * 4);
    __nv_bfloat162 H0, H1, L0, L1;
    split2(v.x, v.y, H0, L0);
    split2(v.z, v.w, H1, L1);
    __nv_bfloat16* o = out + (size_t)r * 3 * K + f * 4;
    ((__nv_bfloat162*)o)[0] = H0;  ((__nv_bfloat162*)o)[1] = H1;   // seg0: hi
    if (loMid) {
        ((__nv_bfloat162*)(o + K))[0] = L0;     ((__nv_bfloat162*)(o + K))[1] = L1;      // lo
        ((__nv_bfloat162*)(o + 2 * K))[0] = H0; ((__nv_bfloat162*)(o + 2 * K))[1] = H1;  // hi
    } else {
        ((__nv_bfloat162*)(o + K))[0] = H0;     ((__nv_bfloat162*)(o + K))[1] = H1;      // hi
        ((__nv_bfloat162*)(o + 2 * K))[0] = L0; ((__nv_bfloat162*)(o + 2 * K))[1] = L1;  // lo
    }
}

// ================= bf16 GEMM: C[M,N] = A[M,K3] @ B[N,K3]^T + bias =================
// 128x128x32 tiles, 8 warps (4m x 2n), 3-stage cp.async. Smem rows padded to 80B.
__global__ __launch_bounds__(256, 2)
void mma_gemm(const __nv_bfloat16* __restrict__ A, const __nv_bfloat16* __restrict__ B,
              const float* __restrict__ bias, float* __restrict__ C,
              int M, int N, int K3) {
    extern __shared__ char sm[];
    const uint32_t sb = smem_u32(sm);
    const int tid = threadIdx.x, wid = tid >> 5, lane = tid & 31;
    const int wm = wid & 3, wn = wid >> 2;
    const int mBase = blockIdx.y * 128, nBase = blockIdx.x * 128;
    const int NIT = K3 / 32;

    float acc[2][8][4] = {};

    auto load_stage = [&](int st, int k0) {
        uint32_t sA = sb + st * 20480, sB = sA + 10240;
#pragma unroll
        for (int i2 = 0; i2 < 2; i2++) {
            int c = tid + i2 * 256;
            int row = c >> 2, kc = c & 3;
            cp16(sA + row * 80 + kc * 16, A + (size_t)(mBase + row) * K3 + k0 + kc * 8);
            cp16(sB + row * 80 + kc * 16, B + (size_t)(nBase + row) * K3 + k0 + kc * 8);
        }
    };

    load_stage(0, 0);  cp_commit();
    load_stage(1, 32); cp_commit();

    for (int it = 0; it < NIT; it++) {
        cp_wait1();
        __syncthreads();
        if (it + 2 < NIT) load_stage((it + 2) % 3, (it + 2) * 32);
        cp_commit();

        uint32_t sA = sb + (it % 3) * 20480, sB = sA + 10240;
#pragma unroll
        for (int kk = 0; kk < 2; kk++) {
            uint32_t a[2][4], bq[4][4];
#pragma unroll
            for (int mt = 0; mt < 2; mt++)
                ldsm4(a[mt], sA + (wm * 32 + mt * 16 + (lane & 15)) * 80 + kk * 32 + (lane >> 4) * 16);
#pragma unroll
            for (int p = 0; p < 4; p++)
                ldsm4(bq[p], sB + (wn * 64 + p * 16 + (lane & 15)) * 80 + kk * 32 + (lane >> 4) * 16);
#pragma unroll
            for (int mt = 0; mt < 2; mt++)
#pragma unroll
                for (int nt = 0; nt < 8; nt++) {
                    int p = nt >> 1, j = nt & 1;
                    mma16816(acc[mt][nt], a[mt], bq[p][j], bq[p][j + 2]);
                }
        }
    }

    // epilogue
    const int cbase = nBase + wn * 64;
#pragma unroll
    for (int nt = 0; nt < 8; nt++) {
        int col = cbase + nt * 8 + 2 * (lane & 3);
        float2 bv = *(const float2*)(bias + col);
#pragma unroll
        for (int mt = 0; mt < 2; mt++) {
            int r = mBase + wm * 32 + mt * 16 + (lane >> 2);
            float2 v0; v0.x = acc[mt][nt][0] + bv.x; v0.y = acc[mt][nt][1] + bv.y;
            float2 v1; v1.x = acc[mt][nt][2] + bv.x; v1.y = acc[mt][nt][3] + bv.y;
            *(float2*)(C + (size_t)r * N + col) = v0;
            *(float2*)(C + (size_t)(r + 8) * N + col) = v1;
        }
    }
}

// ================= flash attention with mma.sync + split-bf16 =================
// (validated: agreed with proven FFMA attention to ~1e-5 in R3/R4 differential)
#define ATT_SMEM 96512

__global__ __launch_bounds__(256, 1)
void attn_mma(const float* __restrict__ qkv, float* __restrict__ ao) {
    extern __shared__ char sm[];
    const uint32_t sb = smem_u32(sm);
    __nv_bfloat16* Pb = (__nv_bfloat16*)(sm);            // also Q2 buffer, [64][200], [hi|lo|hi]
    __nv_bfloat16* Kb = (__nv_bfloat16*)(sm + 25600);    // [64][200], [hi|hi|lo]
    __nv_bfloat16* Vb = (__nv_bfloat16*)(sm + 51200);    // [192][72], rows [Vh;Vh;Vl]
    float* Sb = (float*)(sm + 78848);                    // [64][68]
    float* Al = (float*)(sm + 96256);                    // [64]
    const uint32_t Pu = sb, Ku = sb + 25600, Vu = sb + 51200;

    const int tid = threadIdx.x, wid = tid >> 5, lane = tid & 31;
    const int wm = wid >> 1, wn = wid & 1;
    const int rg = tid >> 4, cg = tid & 15;
    const int bh = blockIdx.y, b = bh / 12, h = bh % 12;
    const int q0 = blockIdx.x * 64;
    const size_t RS = 2304;
    const float scale = 0.125f;

    // ---- load + split Q into Pb (as [Qh|Ql|Qh], pitch 200) ----
    const float* qp = qkv + ((size_t)(b * 2048 + q0)) * RS + h * 64;
#pragma unroll
    for (int i = 0; i < 4; i++) {
        int lin = tid + i * 256;
        int r = lin >> 4, f = lin & 15;
        float4 v = *(const float4*)(qp + (size_t)r * RS + f * 4);
        __nv_bfloat162 H0, H1, L0, L1;
        split2(v.x, v.y, H0, L0); split2(v.z, v.w, H1, L1);
        __nv_bfloat16* base = Pb + r * 200 + f * 4;
        ((__nv_bfloat162*)base)[0] = H0;          ((__nv_bfloat162*)base)[1] = H1;
        ((__nv_bfloat162*)(base + 64))[0] = L0;   ((__nv_bfloat162*)(base + 64))[1] = L1;
        ((__nv_bfloat162*)(base + 128))[0] = H0;  ((__nv_bfloat162*)(base + 128))[1] = H1;
    }
    __syncthreads();

    // ---- preload Q fragments into registers (frees Pb for P') ----
    uint32_t aq[12][4];
#pragma unroll
    for (int ks = 0; ks < 12; ks++)
        ldsm4(aq[ks], Pu + (wm * 16 + (lane & 15)) * 400 + ks * 32 + (lane >> 4) * 16);

    float oc[4][4] = {};
    float mrow[4], lrow[4];
#pragma unroll
    for (int rr = 0; rr < 4; rr++) { mrow[rr] = -1e30f; lrow[rr] = 0.f; }

    for (int kt = 0; kt < 32; kt++) {
        __syncthreads();  // previous tile's reads of Kb/Vb/Sb/Al done

        // ---- load + split K -> Kb ([Kh|Kh|Kl]), V -> Vb ([Vh;Vh;Vl]) ----
        const float* kp = qkv + ((size_t)(b * 2048 + kt * 64)) * RS + 768 + h * 64;
        const float* vp = kp + 768;
#pragma unroll
        for (int i = 0; i < 4; i++) {
            int lin = tid + i * 256;
            int s = lin >> 4, f = lin & 15;
            float4 kv = *(const float4*)(kp + (size_t)s * RS + f * 4);
            __nv_bfloat162 H0, H1, L0, L1;
            split2(kv.x, kv.y, H0, L0); split2(kv.z, kv.w, H1, L1);
            __nv_bfloat16* kb = Kb + s * 200 + f * 4;
            ((__nv_bfloat162*)kb)[0] = H0;         ((__nv_bfloat162*)kb)[1] = H1;
            ((__nv_bfloat162*)(kb + 64))[0] = H0;  ((__nv_bfloat162*)(kb + 64))[1] = H1;
            ((__nv_bfloat162*)(kb + 128))[0] = L0; ((__nv_bfloat162*)(kb + 128))[1] = L1;

            float4 vv = *(const float4*)(vp + (size_t)s * RS + f * 4);
            split2(vv.x, vv.y, H0, L0); split2(vv.z, vv.w, H1, L1);
            __nv_bfloat16* v0 = Vb + s * 72 + f * 4;
            ((__nv_bfloat162*)v0)[0] = H0; ((__nv_bfloat162*)v0)[1] = H1;
            __nv_bfloat16* v1 = Vb + (64 + s) * 72 + f * 4;
            ((__nv_bfloat162*)v1)[0] = H0; ((__nv_bfloat162*)v1)[1] = H1;
            __nv_bfloat16* v2 = Vb + (128 + s) * 72 + f * 4;
            ((__nv_bfloat162*)v2)[0] = L0; ((__nv_bfloat162*)v2)[1] = L1;
        }
        __syncthreads();

        // ---- S = Q' @ K'^T (rows wm*16+16, key cols wn*32+32) ----
        float sc[4][4] = {};
#pragma unroll
        for (int ks = 0; ks < 12; ks++) {
            uint32_t bk[2][4];
#pragma unroll
            for (int p = 0; p < 2; p++)
                ldsm4(bk[p], Ku + (wn * 32 + p * 16 + (lane & 15)) * 400 + ks * 32 + (lane >> 4) * 16);
#pragma unroll
            for (int nt = 0; nt < 4; nt++) {
                int p = nt >> 1, j = nt & 1;
                mma16816(sc[nt], aq[ks], bk[p][j], bk[p][j + 2]);
            }
        }
        // store S fragments
        {
            int r = wm * 16 + (lane >> 2);
            int cb = wn * 32 + 2 * (lane & 3);
#pragma unroll
            for (int nt = 0; nt < 4; nt++) {
                float2 v0; v0.x = sc[nt][0]; v0.y = sc[nt][1];
                float2 v1; v1.x = sc[nt][2]; v1.y = sc[nt][3];
                *(float2*)(Sb + r * 68 + cb + nt * 8) = v0;
                *(float2*)(Sb + (r + 8) * 68 + cb + nt * 8) = v1;
            }
        }
        __syncthreads();

        // ---- online softmax (rg/cg layout) ----
#pragma unroll
        for (int rr = 0; rr < 4; rr++) {
            int row = rg * 4 + rr;
            const float* srow = Sb + row * 68 + cg;
            float t0 = srow[0] * scale, t1 = srow[16] * scale;
            float t2 = srow[32] * scale, t3 = srow[48] * scale;
            float mloc = fmaxf(fmaxf(t0, t1), fmaxf(t2, t3));
#pragma unroll
            for (int off = 8; off >= 1; off >>= 1)
                mloc = fmaxf(mloc, __shfl_xor_sync(0xffffffffu, mloc, off, 16));
            float mnew = fmaxf(mrow[rr], mloc);
            float alpha = __expf(mrow[rr] - mnew);
            mrow[rr] = mnew;

            float p0 = __expf(t0 - mnew), p1 = __expf(t1 - mnew);
            float p2 = __expf(t2 - mnew), p3 = __expf(t3 - mnew);

            __nv_bfloat16* prow = Pb + row * 200;
#pragma unroll
            for (int cc = 0; cc < 4; cc++) {
                float pv = (cc == 0) ? p0 : (cc == 1) ? p1 : (cc == 2) ? p2 : p3;
                __nv_bfloat16 ph = __float2bfloat16(pv);
                __nv_bfloat16 pl = __float2bfloat16(pv - __bfloat162float(ph));
                int c = cg + 16 * cc;
                prow[c] = ph;
                prow[64 + c] = pl;
                prow[128 + c] = ph;
            }
            float lloc = (p0 + p1) + (p2 + p3);
#pragma unroll
            for (int off = 8; off >= 1; off >>= 1)
                lloc += __shfl_xor_sync(0xffffffffu, lloc, off, 16);
            lrow[rr] = lrow[rr] * alpha + lloc;
            if (cg == 0) Al[row] = alpha;
        }
        __syncthreads();

        // ---- rescale O fragments by alpha of their rows ----
        {
            int r = wm * 16 + (lane >> 2);
            float a1 = Al[r], a2 = Al[r + 8];
#pragma unroll
            for (int nt = 0; nt < 4; nt++) {
                oc[nt][0] *= a1; oc[nt][1] *= a1;
                oc[nt][2] *= a2; oc[nt][3] *= a2;
            }
        }

        // ---- O += P' @ V2 (d cols wn*32+32) ----
#pragma unroll
        for (int ks = 0; ks < 12; ks++) {
            uint32_t ap[4];
            ldsm4(ap, Pu + (wm * 16 + (lane & 15)) * 400 + ks * 32 + (lane >> 4) * 16);
            uint32_t bv2[2][4];
#pragma unroll
            for (int p = 0; p < 2; p++)
                ldsm4t(bv2[p], Vu + (ks * 16 + (lane & 15)) * 144 + wn * 64 + p * 32 + (lane >> 4) * 16);
#pragma unroll
            for (int nt = 0; nt < 4; nt++) {
                int p = nt >> 1, j = nt & 1;
                mma16816(oc[nt], ap, bv2[p][j * 2], bv2[p][j * 2 + 1]);
            }
        }
    }

    // ---- finalize: 1/l and store ----
#pragma unroll
    for (int rr = 0; rr < 4; rr++)
        if (cg == 0) Al[rg * 4 + rr] = 1.0f / lrow[rr];
    __syncthreads();
    {
        int r = wm * 16 + (lane >> 2);
        float i1 = Al[r], i2 = Al[r + 8];
        int grow = b * 2048 + q0;
#pragma unroll
        for (int nt = 0; nt < 4; nt++) {
            int col = h * 64 + wn * 32 + nt * 8 + 2 * (lane & 3);
            float2 v0; v0.x = oc[nt][0] * i1; v0.y = oc[nt][1] * i1;
            float2 v1; v1.x = oc[nt][2] * i2; v1.y = oc[nt][3] * i2;
            *(float2*)(ao + (size_t)(grow + r) * 768 + col) = v0;
            *(float2*)(ao + (size_t)(grow + r + 8) * 768 + col) = v1;
        }
    }
}

// ---------------- launch ----------------
extern "C" void kernel_launch(void* const* d_in, const int* in_sizes, int n_in,
                              void* d_out, int out_size) {
    const float* x      = (const float*)d_in[0];
    const float* qkv_w  = (const float*)d_in[1];
    const float* qkv_b  = (const float*)d_in[2];
    const float* proj_w = (const float*)d_in[3];
    const float* proj_b = (const float*)d_in[4];
    float* out = (float*)d_out;

    float *qkv, *ao;
    __nv_bfloat16 *A2, *B1, *B2;
    cudaGetSymbolAddress((void**)&qkv, g_qkv);
    cudaGetSymbolAddress((void**)&ao,  g_ao);
    cudaGetSymbolAddress((void**)&A2,  g_A2);
    cudaGetSymbolAddress((void**)&B1,  g_B1);
    cudaGetSymbolAddress((void**)&B2,  g_B2);

    const int gemm_smem = 3 * 20480;  // 61440
    cudaFuncSetAttribute(mma_gemm, cudaFuncAttributeMaxDynamicSharedMemorySize, gemm_smem);
    cudaFuncSetAttribute(attn_mma, cudaFuncAttributeMaxDynamicSharedMemorySize, ATT_SMEM);

    // A-operands: [hi|lo|hi] ; B-operands (weights): [hi|hi|lo]
    split3<<<(4096 * 192 + 255) / 256, 256>>>(x, A2, 4096, 768, 1);
    split3<<<(2304 * 192 + 255) / 256, 256>>>(qkv_w, B1, 2304, 768, 0);

    // 1) qkv = x @ qkv_w^T + qkv_b   (K' = 2304)
    mma_gemm<<<dim3(18, 32), 256, gemm_smem>>>(A2, B1, qkv_b, qkv, 4096, 2304, 2304);

    // 2) attention -> ao
    attn_mma<<<dim3(32, 24), 256, ATT_SMEM>>>(qkv, ao);

    // split ao and proj_w
    split3<<<(4096 * 192 + 255) / 256, 256>>>(ao, A2, 4096, 768, 1);
    split3<<<(768 * 192 + 255) / 256, 256>>>(proj_w, B2, 768, 768, 0);

    // 3) out = ao @ proj_w^T + proj_b
    mma_gemm<<<dim3(6, 32), 256, gemm_smem>>>(A2, B2, proj_b, out, 4096, 768, 2304);
}

// round 6
// speedup vs baseline: 1.9330x; 1.2354x over previous
#include <cuda_runtime.h>
#include <cuda_bf16.h>
#include <cstdint>

// ---------------- scratch (no cudaMalloc allowed) ----------------
__device__ float g_qkv[4096 * 2304];                 // fp32 qkv
__device__ float g_ao [4096 * 768];                  // fp32 attention out
__device__ __nv_bfloat16 g_A2[4096 * 2304];          // activations split-concat [M][3K] = [hi|lo|hi]
__device__ __nv_bfloat16 g_B1[2304 * 2304];          // qkv_w split-concat [hi|hi|lo]
__device__ __nv_bfloat16 g_B2[768 * 2304];           // proj_w split-concat [hi|hi|lo]
// per-head split buffers: [24][2048][128] bf16, cols 0-63 = hi, 64-127 = lo
__device__ __nv_bfloat16 g_Q2[24 * 2048 * 128];
__device__ __nv_bfloat16 g_K2[24 * 2048 * 128];
__device__ __nv_bfloat16 g_V2[24 * 2048 * 128];

// ================= helpers =================
__device__ __forceinline__ uint32_t smem_u32(const void* p) {
    uint32_t a;
    asm("{ .reg .u64 t; cvta.to.shared.u64 t, %1; cvt.u32.u64 %0, t; }" : "=r"(a) : "l"(p));
    return a;
}
__device__ __forceinline__ void ldsm4(uint32_t* r, uint32_t a) {
    asm volatile("ldmatrix.sync.aligned.m8n8.x4.shared.b16 {%0,%1,%2,%3}, [%4];"
                 : "=r"(r[0]), "=r"(r[1]), "=r"(r[2]), "=r"(r[3]) : "r"(a));
}
__device__ __forceinline__ void ldsm4t(uint32_t* r, uint32_t a) {
    asm volatile("ldmatrix.sync.aligned.m8n8.x4.trans.shared.b16 {%0,%1,%2,%3}, [%4];"
                 : "=r"(r[0]), "=r"(r[1]), "=r"(r[2]), "=r"(r[3]) : "r"(a));
}
__device__ __forceinline__ void mma16816(float* d, const uint32_t* a, uint32_t b0, uint32_t b1) {
    asm volatile("mma.sync.aligned.m16n8k16.row.col.f32.bf16.bf16.f32 "
                 "{%0,%1,%2,%3},{%4,%5,%6,%7},{%8,%9},{%0,%1,%2,%3};"
                 : "+f"(d[0]), "+f"(d[1]), "+f"(d[2]), "+f"(d[3])
                 : "r"(a[0]), "r"(a[1]), "r"(a[2]), "r"(a[3]), "r"(b0), "r"(b1));
}
__device__ __forceinline__ void cp16(uint32_t saddr, const void* gaddr) {
    asm volatile("cp.async.cg.shared.global [%0], [%1], 16;" :: "r"(saddr), "l"(gaddr));
}
__device__ __forceinline__ void cp_commit() { asm volatile("cp.async.commit_group;" ::: "memory"); }
__device__ __forceinline__ void cp_wait1()  { asm volatile("cp.async.wait_group 1;" ::: "memory"); }
__device__ __forceinline__ void cp_wait0()  { asm volatile("cp.async.wait_group 0;" ::: "memory"); }

__device__ __forceinline__ void split2(float x, float y, __nv_bfloat162& hi, __nv_bfloat162& lo) {
    __nv_bfloat16 hx = __float2bfloat16(x), hy = __float2bfloat16(y);
    hi.x = hx; hi.y = hy;
    lo.x = __float2bfloat16(x - __bfloat162float(hx));
    lo.y = __float2bfloat16(y - __bfloat162float(hy));
}

// ===== split-concat: in[R][K] f32 -> out[R][3K] bf16 (for GEMM operands) =====
__global__ void split3(const float* __restrict__ in, __nv_bfloat16* __restrict__ out,
                       int R, int K, int loMid) {
    int i = blockIdx.x * blockDim.x + threadIdx.x;
    int per_row = K >> 2;
    if (i >= R * per_row) return;
    int r = i / per_row, f = i % per_row;
    float4 v = *(const float4*)(in + (size_t)r * K + f * 4);
    __nv_bfloat162 H0, H1, L0, L1;
    split2(v.x, v.y, H0, L0);
    split2(v.z, v.w, H1, L1);
    __nv_bfloat16* o = out + (size_t)r * 3 * K + f * 4;
    ((__nv_bfloat162*)o)[0] = H0;  ((__nv_bfloat162*)o)[1] = H1;
    if (loMid) {
        ((__nv_bfloat162*)(o + K))[0] = L0;     ((__nv_bfloat162*)(o + K))[1] = L1;
        ((__nv_bfloat162*)(o + 2 * K))[0] = H0; ((__nv_bfloat162*)(o + 2 * K))[1] = H1;
    } else {
        ((__nv_bfloat162*)(o + K))[0] = H0;     ((__nv_bfloat162*)(o + K))[1] = H1;
        ((__nv_bfloat162*)(o + 2 * K))[0] = L0; ((__nv_bfloat162*)(o + 2 * K))[1] = L1;
    }
}

// ===== per-head split: g_qkv [4096][2304] f32 -> Q2/K2/V2 [24][2048][128] bf16 (hi|lo) =====
__global__ void splitQKV(const float* __restrict__ qkv,
                         __nv_bfloat16* __restrict__ Q2, __nv_bfloat16* __restrict__ K2,
                         __nv_bfloat16* __restrict__ V2) {
    int i = blockIdx.x * blockDim.x + threadIdx.x;
    if (i >= 4096 * 576) return;
    int row = i / 576, c4 = i % 576;
    int col = c4 * 4;
    int m = col / 768;
    int hc = col - m * 768;
    int h = hc >> 6, d = hc & 63;
    float4 v = *(const float4*)(qkv + (size_t)row * 2304 + col);
    __nv_bfloat162 H0, H1, L0, L1;
    split2(v.x, v.y, H0, L0);
    split2(v.z, v.w, H1, L1);
    __nv_bfloat16* base = (m == 0 ? Q2 : m == 1 ? K2 : V2);
    __nv_bfloat16* dst = base + ((size_t)((row >> 11) * 12 + h) * 2048 + (row & 2047)) * 128 + d;
    ((__nv_bfloat162*)dst)[0] = H0;        ((__nv_bfloat162*)dst)[1] = H1;
    ((__nv_bfloat162*)(dst + 64))[0] = L0; ((__nv_bfloat162*)(dst + 64))[1] = L1;
}

// ================= bf16 GEMM (validated R5) =================
__global__ __launch_bounds__(256, 2)
void mma_gemm(const __nv_bfloat16* __restrict__ A, const __nv_bfloat16* __restrict__ B,
              const float* __restrict__ bias, float* __restrict__ C,
              int M, int N, int K3) {
    extern __shared__ char sm[];
    const uint32_t sb = smem_u32(sm);
    const int tid = threadIdx.x, wid = tid >> 5, lane = tid & 31;
    const int wm = wid & 3, wn = wid >> 2;
    const int mBase = blockIdx.y * 128, nBase = blockIdx.x * 128;
    const int NIT = K3 / 32;

    float acc[2][8][4] = {};

    auto load_stage = [&](int st, int k0) {
        uint32_t sA = sb + st * 20480, sB = sA + 10240;
#pragma unroll
        for (int i2 = 0; i2 < 2; i2++) {
            int c = tid + i2 * 256;
            int row = c >> 2, kc = c & 3;
            cp16(sA + row * 80 + kc * 16, A + (size_t)(mBase + row) * K3 + k0 + kc * 8);
            cp16(sB + row * 80 + kc * 16, B + (size_t)(nBase + row) * K3 + k0 + kc * 8);
        }
    };

    load_stage(0, 0);  cp_commit();
    load_stage(1, 32); cp_commit();

    for (int it = 0; it < NIT; it++) {
        cp_wait1();
        __syncthreads();
        if (it + 2 < NIT) load_stage((it + 2) % 3, (it + 2) * 32);
        cp_commit();

        uint32_t sA = sb + (it % 3) * 20480, sB = sA + 10240;
#pragma unroll
        for (int kk = 0; kk < 2; kk++) {
            uint32_t a[2][4], bq[4][4];
#pragma unroll
            for (int mt = 0; mt < 2; mt++)
                ldsm4(a[mt], sA + (wm * 32 + mt * 16 + (lane & 15)) * 80 + kk * 32 + (lane >> 4) * 16);
#pragma unroll
            for (int p = 0; p < 4; p++)
                ldsm4(bq[p], sB + (wn * 64 + p * 16 + (lane & 15)) * 80 + kk * 32 + (lane >> 4) * 16);
#pragma unroll
            for (int mt = 0; mt < 2; mt++)
#pragma unroll
                for (int nt = 0; nt < 8; nt++) {
                    int p = nt >> 1, j = nt & 1;
                    mma16816(acc[mt][nt], a[mt], bq[p][j], bq[p][j + 2]);
                }
        }
    }

    const int cbase = nBase + wn * 64;
#pragma unroll
    for (int nt = 0; nt < 8; nt++) {
        int col = cbase + nt * 8 + 2 * (lane & 3);
        float2 bv = *(const float2*)(bias + col);
#pragma unroll
        for (int mt = 0; mt < 2; mt++) {
            int r = mBase + wm * 32 + mt * 16 + (lane >> 2);
            float2 v0; v0.x = acc[mt][nt][0] + bv.x; v0.y = acc[mt][nt][1] + bv.y;
            float2 v1; v1.x = acc[mt][nt][2] + bv.x; v1.y = acc[mt][nt][3] + bv.y;
            *(float2*)(C + (size_t)r * N + col) = v0;
            *(float2*)(C + (size_t)(r + 8) * N + col) = v1;
        }
    }
}

// ================= flash attention v2: dedup split + cp.async + 2 CTAs/SM =================
// smem: Qb[64][272B]@0  Kb@17408  Pb@34816  Vb[128][144B]@52224  Sb[64][68]f32@70656  Al@88064
// physical layouts: Q/K/P: cols 0-63 hi, 64-127 lo (pitch 136 bf16 = 272B)
//                   V: rows 0-63 hi, 64-127 lo (pitch 72 bf16 = 144B)
// virtual 12-step K-dim pairing (per 16-wide ks step):
//   S  = sum: (Qh,Kh) ks0-3, (Ql,Kh) ks4-7, (Qh,Kl) ks8-11
//   PV = sum: (Ph,Vh) ks0-3, (Pl,Vh) ks4-7, (Ph,Vl) ks8-11
//   A-side group: qg = (ks&3) + (((ks>>2)&1)<<2) ; B-side group: kg = (ks&3) + ((ks>>3)<<2)
#define AT2_SMEM 88320

__global__ __launch_bounds__(256, 2)
void attn2(const __nv_bfloat16* __restrict__ Q2, const __nv_bfloat16* __restrict__ K2,
           const __nv_bfloat16* __restrict__ V2, float* __restrict__ ao) {
    extern __shared__ char sm[];
    const uint32_t sb = smem_u32(sm);
    const uint32_t Qu = sb, Ku = sb + 17408, Pu = sb + 34816, Vu = sb + 52224;
    __nv_bfloat16* Pb = (__nv_bfloat16*)(sm + 34816);
    float* Sb = (float*)(sm + 70656);
    float* Al = (float*)(sm + 88064);

    const int tid = threadIdx.x, wid = tid >> 5, lane = tid & 31;
    const int wm = wid >> 1, wn = wid & 1;
    const int rg = tid >> 4, cg = tid & 15;
    const int bh = blockIdx.y;
    const int q0 = blockIdx.x * 64;
    const float scale = 0.125f;

    // ---- load Q' tile once (resident) ----
    const __nv_bfloat16* Qg = Q2 + ((size_t)bh * 2048 + q0) * 128;
#pragma unroll
    for (int i = 0; i < 4; i++) {
        int idx = tid + i * 256;
        int row = idx >> 4, j = idx & 15;
        cp16(Qu + row * 272 + j * 16, Qg + row * 128 + j * 8);
    }
    cp_commit();
    cp_wait0();
    __syncthreads();

    float oc[4][4] = {};
    float mrow[4], lrow[4];
#pragma unroll
    for (int rr = 0; rr < 4; rr++) { mrow[rr] = -1e30f; lrow[rr] = 0.f; }

    for (int kt = 0; kt < 32; kt++) {
        __syncthreads();  // prior iter's reads of Kb/Vb/Pb done

        const __nv_bfloat16* Kg = K2 + ((size_t)bh * 2048 + kt * 64) * 128;
        const __nv_bfloat16* Vg = V2 + ((size_t)bh * 2048 + kt * 64) * 128;
#pragma unroll
        for (int i = 0; i < 4; i++) {
            int idx = tid + i * 256;
            int row = idx >> 4, j = idx & 15;
            cp16(Ku + row * 272 + j * 16, Kg + row * 128 + j * 8);
        }
#pragma unroll
        for (int i = 0; i < 4; i++) {
            int idx = tid + i * 256;
            int row = idx >> 3, j = idx & 7;
            cp16(Vu + row * 144 + j * 16, Vg + (row & 63) * 128 + (row >> 6) * 64 + j * 8);
        }
        cp_commit();
        cp_wait0();
        __syncthreads();

        // ---- S = Q' @ K'^T ----
        float sc[4][4] = {};
#pragma unroll
        for (int ks = 0; ks < 12; ks++) {
            int qg = (ks & 3) + (((ks >> 2) & 1) << 2);
            int kg = (ks & 3) + ((ks >> 3) << 2);
            uint32_t aq[4], bk0[4], bk1[4];
            ldsm4(aq, Qu + (wm * 16 + (lane & 15)) * 272 + qg * 32 + (lane >> 4) * 16);
            ldsm4(bk0, Ku + (wn * 32 + (lane & 15)) * 272 + kg * 32 + (lane >> 4) * 16);
            ldsm4(bk1, Ku + (wn * 32 + 16 + (lane & 15)) * 272 + kg * 32 + (lane >> 4) * 16);
            mma16816(sc[0], aq, bk0[0], bk0[2]);
            mma16816(sc[1], aq, bk0[1], bk0[3]);
            mma16816(sc[2], aq, bk1[0], bk1[2]);
            mma16816(sc[3], aq, bk1[1], bk1[3]);
        }
        {
            int r = wm * 16 + (lane >> 2);
            int cb = wn * 32 + 2 * (lane & 3);
#pragma unroll
            for (int nt = 0; nt < 4; nt++) {
                float2 v0; v0.x = sc[nt][0]; v0.y = sc[nt][1];
                float2 v1; v1.x = sc[nt][2]; v1.y = sc[nt][3];
                *(float2*)(Sb + r * 68 + cb + nt * 8) = v0;
                *(float2*)(Sb + (r + 8) * 68 + cb + nt * 8) = v1;
            }
        }
        __syncthreads();

        // ---- online softmax (validated rg/cg layout) ----
#pragma unroll
        for (int rr = 0; rr < 4; rr++) {
            int row = rg * 4 + rr;
            const float* srow = Sb + row * 68 + cg;
            float t0 = srow[0] * scale, t1 = srow[16] * scale;
            float t2 = srow[32] * scale, t3 = srow[48] * scale;
            float mloc = fmaxf(fmaxf(t0, t1), fmaxf(t2, t3));
#pragma unroll
            for (int off = 8; off >= 1; off >>= 1)
                mloc = fmaxf(mloc, __shfl_xor_sync(0xffffffffu, mloc, off, 16));
            float mnew = fmaxf(mrow[rr], mloc);
            float alpha = __expf(mrow[rr] - mnew);
            mrow[rr] = mnew;

            float p0 = __expf(t0 - mnew), p1 = __expf(t1 - mnew);
            float p2 = __expf(t2 - mnew), p3 = __expf(t3 - mnew);

            __nv_bfloat16* prow = Pb + row * 136;
#pragma unroll
            for (int cc = 0; cc < 4; cc++) {
                float pv = (cc == 0) ? p0 : (cc == 1) ? p1 : (cc == 2) ? p2 : p3;
                __nv_bfloat16 ph = __float2bfloat16(pv);
                __nv_bfloat16 pl = __float2bfloat16(pv - __bfloat162float(ph));
                int c = cg + 16 * cc;
                prow[c] = ph;
                prow[64 + c] = pl;
            }
            float lloc = (p0 + p1) + (p2 + p3);
#pragma unroll
            for (int off = 8; off >= 1; off >>= 1)
                lloc += __shfl_xor_sync(0xffffffffu, lloc, off, 16);
            lrow[rr] = lrow[rr] * alpha + lloc;
            if (cg == 0) Al[row] = alpha;
        }
        __syncthreads();

        // ---- rescale O, then O += P' @ V' ----
        {
            int r = wm * 16 + (lane >> 2);
            float a1 = Al[r], a2 = Al[r + 8];
#pragma unroll
            for (int nt = 0; nt < 4; nt++) {
                oc[nt][0] *= a1; oc[nt][1] *= a1;
                oc[nt][2] *= a2; oc[nt][3] *= a2;
            }
        }
#pragma unroll
        for (int ks = 0; ks < 12; ks++) {
            int pg = (ks & 3) + (((ks >> 2) & 1) << 2);
            int vg = (ks & 3) + ((ks >> 3) << 2);
            uint32_t ap[4];
            ldsm4(ap, Pu + (wm * 16 + (lane & 15)) * 272 + pg * 32 + (lane >> 4) * 16);
            uint32_t bv2[2][4];
#pragma unroll
            for (int p = 0; p < 2; p++)
                ldsm4t(bv2[p], Vu + (vg * 16 + (lane & 15)) * 144 + wn * 64 + p * 32 + (lane >> 4) * 16);
#pragma unroll
            for (int nt = 0; nt < 4; nt++) {
                int p = nt >> 1, j = nt & 1;
                mma16816(oc[nt], ap, bv2[p][j * 2], bv2[p][j * 2 + 1]);
            }
        }
    }

    // ---- finalize ----
#pragma unroll
    for (int rr = 0; rr < 4; rr++)
        if (cg == 0) Al[rg * 4 + rr] = 1.0f / lrow[rr];
    __syncthreads();
    {
        int b = bh / 12, h = bh % 12;
        int r = wm * 16 + (lane >> 2);
        float i1 = Al[r], i2 = Al[r + 8];
        int grow = b * 2048 + q0;
#pragma unroll
        for (int nt = 0; nt < 4; nt++) {
            int col = h * 64 + wn * 32 + nt * 8 + 2 * (lane & 3);
            float2 v0; v0.x = oc[nt][0] * i1; v0.y = oc[nt][1] * i1;
            float2 v1; v1.x = oc[nt][2] * i2; v1.y = oc[nt][3] * i2;
            *(float2*)(ao + (size_t)(grow + r) * 768 + col) = v0;
            *(float2*)(ao + (size_t)(grow + r + 8) * 768 + col) = v1;
        }
    }
}

// ---------------- launch ----------------
extern "C" void kernel_launch(void* const* d_in, const int* in_sizes, int n_in,
                              void* d_out, int out_size) {
    const float* x      = (const float*)d_in[0];
    const float* qkv_w  = (const float*)d_in[1];
    const float* qkv_b  = (const float*)d_in[2];
    const float* proj_w = (const float*)d_in[3];
    const float* proj_b = (const float*)d_in[4];
    float* out = (float*)d_out;

    float *qkv, *ao;
    __nv_bfloat16 *A2, *B1, *B2, *Q2, *K2, *V2;
    cudaGetSymbolAddress((void**)&qkv, g_qkv);
    cudaGetSymbolAddress((void**)&ao,  g_ao);
    cudaGetSymbolAddress((void**)&A2,  g_A2);
    cudaGetSymbolAddress((void**)&B1,  g_B1);
    cudaGetSymbolAddress((void**)&B2,  g_B2);
    cudaGetSymbolAddress((void**)&Q2,  g_Q2);
    cudaGetSymbolAddress((void**)&K2,  g_K2);
    cudaGetSymbolAddress((void**)&V2,  g_V2);

    const int gemm_smem = 3 * 20480;  // 61440
    cudaFuncSetAttribute(mma_gemm, cudaFuncAttributeMaxDynamicSharedMemorySize, gemm_smem);
    cudaFuncSetAttribute(attn2, cudaFuncAttributeMaxDynamicSharedMemorySize, AT2_SMEM);

    // A-operands: [hi|lo|hi] ; B-operands (weights): [hi|hi|lo]
    split3<<<(4096 * 192 + 255) / 256, 256>>>(x, A2, 4096, 768, 1);
    split3<<<(2304 * 192 + 255) / 256, 256>>>(qkv_w, B1, 2304, 768, 0);

    // 1) qkv = x @ qkv_w^T + qkv_b   (K' = 2304)
    mma_gemm<<<dim3(18, 32), 256, gemm_smem>>>(A2, B1, qkv_b, qkv, 4096, 2304, 2304);

    // 1.5) per-head hi/lo split of q,k,v
    splitQKV<<<(4096 * 576 + 255) / 256, 256>>>(qkv, Q2, K2, V2);

    // 2) attention -> ao
    attn2<<<dim3(32, 24), 256, AT2_SMEM>>>(Q2, K2, V2, ao);

    // split ao and proj_w
    split3<<<(4096 * 192 + 255) / 256, 256>>>(ao, A2, 4096, 768, 1);
    split3<<<(768 * 192 + 255) / 256, 256>>>(proj_w, B2, 768, 768, 0);

    // 3) out = ao @ proj_w^T + proj_b
    mma_gemm<<<dim3(6, 32), 256, gemm_smem>>>(A2, B2, proj_b, out, 4096, 768, 2304);
}

// round 7
// speedup vs baseline: 2.2818x; 1.1805x over previous
#include <cuda_runtime.h>
#include <cuda_bf16.h>
#include <cstdint>

// ---------------- scratch (no cudaMalloc allowed) ----------------
__device__ float g_qkv[4096 * 2304];
__device__ float g_ao [4096 * 768];
__device__ __nv_bfloat16 g_A2[4096 * 2304];
__device__ __nv_bfloat16 g_B1[2304 * 2304];
__device__ __nv_bfloat16 g_B2[768 * 2304];
__device__ __nv_bfloat16 g_Q2[24 * 2048 * 128];
__device__ __nv_bfloat16 g_K2[24 * 2048 * 128];
__device__ __nv_bfloat16 g_V2[24 * 2048 * 128];

// ================= helpers =================
__device__ __forceinline__ uint32_t smem_u32(const void* p) {
    uint32_t a;
    asm("{ .reg .u64 t; cvta.to.shared.u64 t, %1; cvt.u32.u64 %0, t; }" : "=r"(a) : "l"(p));
    return a;
}
__device__ __forceinline__ void ldsm4(uint32_t* r, uint32_t a) {
    asm volatile("ldmatrix.sync.aligned.m8n8.x4.shared.b16 {%0,%1,%2,%3}, [%4];"
                 : "=r"(r[0]), "=r"(r[1]), "=r"(r[2]), "=r"(r[3]) : "r"(a));
}
__device__ __forceinline__ void ldsm4t(uint32_t* r, uint32_t a) {
    asm volatile("ldmatrix.sync.aligned.m8n8.x4.trans.shared.b16 {%0,%1,%2,%3}, [%4];"
                 : "=r"(r[0]), "=r"(r[1]), "=r"(r[2]), "=r"(r[3]) : "r"(a));
}
__device__ __forceinline__ void mma16816(float* d, const uint32_t* a, uint32_t b0, uint32_t b1) {
    asm volatile("mma.sync.aligned.m16n8k16.row.col.f32.bf16.bf16.f32 "
                 "{%0,%1,%2,%3},{%4,%5,%6,%7},{%8,%9},{%0,%1,%2,%3};"
                 : "+f"(d[0]), "+f"(d[1]), "+f"(d[2]), "+f"(d[3])
                 : "r"(a[0]), "r"(a[1]), "r"(a[2]), "r"(a[3]), "r"(b0), "r"(b1));
}
__device__ __forceinline__ void cp16(uint32_t saddr, const void* gaddr) {
    asm volatile("cp.async.cg.shared.global [%0], [%1], 16;" :: "r"(saddr), "l"(gaddr));
}
__device__ __forceinline__ void cp_commit() { asm volatile("cp.async.commit_group;" ::: "memory"); }
__device__ __forceinline__ void cp_wait1()  { asm volatile("cp.async.wait_group 1;" ::: "memory"); }
__device__ __forceinline__ void cp_wait0()  { asm volatile("cp.async.wait_group 0;" ::: "memory"); }

__device__ __forceinline__ void split2(float x, float y, __nv_bfloat162& hi, __nv_bfloat162& lo) {
    __nv_bfloat16 hx = __float2bfloat16(x), hy = __float2bfloat16(y);
    hi.x = hx; hi.y = hy;
    lo.x = __float2bfloat16(x - __bfloat162float(hx));
    lo.y = __float2bfloat16(y - __bfloat162float(hy));
}
__device__ __forceinline__ uint32_t packbf(float x, float y) {
    __nv_bfloat162 h; h.x = __float2bfloat16(x); h.y = __float2bfloat16(y);
    return *(uint32_t*)&h;
}

// ===== split-concat for GEMM operands =====
__global__ void split3(const float* __restrict__ in, __nv_bfloat16* __restrict__ out,
                       int R, int K, int loMid) {
    int i = blockIdx.x * blockDim.x + threadIdx.x;
    int per_row = K >> 2;
    if (i >= R * per_row) return;
    int r = i / per_row, f = i % per_row;
    float4 v = *(const float4*)(in + (size_t)r * K + f * 4);
    __nv_bfloat162 H0, H1, L0, L1;
    split2(v.x, v.y, H0, L0);
    split2(v.z, v.w, H1, L1);
    __nv_bfloat16* o = out + (size_t)r * 3 * K + f * 4;
    ((__nv_bfloat162*)o)[0] = H0;  ((__nv_bfloat162*)o)[1] = H1;
    if (loMid) {
        ((__nv_bfloat162*)(o + K))[0] = L0;     ((__nv_bfloat162*)(o + K))[1] = L1;
        ((__nv_bfloat162*)(o + 2 * K))[0] = H0; ((__nv_bfloat162*)(o + 2 * K))[1] = H1;
    } else {
        ((__nv_bfloat162*)(o + K))[0] = H0;     ((__nv_bfloat162*)(o + K))[1] = H1;
        ((__nv_bfloat162*)(o + 2 * K))[0] = L0; ((__nv_bfloat162*)(o + 2 * K))[1] = L1;
    }
}

// ===== per-head split: qkv f32 -> Q2/K2/V2 [24][2048][128] bf16 (hi|lo) =====
__global__ void splitQKV(const float* __restrict__ qkv,
                         __nv_bfloat16* __restrict__ Q2, __nv_bfloat16* __restrict__ K2,
                         __nv_bfloat16* __restrict__ V2) {
    int i = blockIdx.x * blockDim.x + threadIdx.x;
    if (i >= 4096 * 576) return;
    int row = i / 576, c4 = i % 576;
    int col = c4 * 4;
    int m = col / 768;
    int hc = col - m * 768;
    int h = hc >> 6, d = hc & 63;
    float4 v = *(const float4*)(qkv + (size_t)row * 2304 + col);
    __nv_bfloat162 H0, H1, L0, L1;
    split2(v.x, v.y, H0, L0);
    split2(v.z, v.w, H1, L1);
    __nv_bfloat16* base = (m == 0 ? Q2 : m == 1 ? K2 : V2);
    __nv_bfloat16* dst = base + ((size_t)((row >> 11) * 12 + h) * 2048 + (row & 2047)) * 128 + d;
    ((__nv_bfloat162*)dst)[0] = H0;        ((__nv_bfloat162*)dst)[1] = H1;
    ((__nv_bfloat162*)(dst + 64))[0] = L0; ((__nv_bfloat162*)(dst + 64))[1] = L1;
}

// ================= bf16 GEMM (validated R5) =================
__global__ __launch_bounds__(256, 2)
void mma_gemm(const __nv_bfloat16* __restrict__ A, const __nv_bfloat16* __restrict__ B,
              const float* __restrict__ bias, float* __restrict__ C,
              int M, int N, int K3) {
    extern __shared__ char sm[];
    const uint32_t sb = smem_u32(sm);
    const int tid = threadIdx.x, wid = tid >> 5, lane = tid & 31;
    const int wm = wid & 3, wn = wid >> 2;
    const int mBase = blockIdx.y * 128, nBase = blockIdx.x * 128;
    const int NIT = K3 / 32;

    float acc[2][8][4] = {};

    auto load_stage = [&](int st, int k0) {
        uint32_t sA = sb + st * 20480, sB = sA + 10240;
#pragma unroll
        for (int i2 = 0; i2 < 2; i2++) {
            int c = tid + i2 * 256;
            int row = c >> 2, kc = c & 3;
            cp16(sA + row * 80 + kc * 16, A + (size_t)(mBase + row) * K3 + k0 + kc * 8);
            cp16(sB + row * 80 + kc * 16, B + (size_t)(nBase + row) * K3 + k0 + kc * 8);
        }
    };

    load_stage(0, 0);  cp_commit();
    load_stage(1, 32); cp_commit();

    for (int it = 0; it < NIT; it++) {
        cp_wait1();
        __syncthreads();
        if (it + 2 < NIT) load_stage((it + 2) % 3, (it + 2) * 32);
        cp_commit();

        uint32_t sA = sb + (it % 3) * 20480, sB = sA + 10240;
#pragma unroll
        for (int kk = 0; kk < 2; kk++) {
            uint32_t a[2][4], bq[4][4];
#pragma unroll
            for (int mt = 0; mt < 2; mt++)
                ldsm4(a[mt], sA + (wm * 32 + mt * 16 + (lane & 15)) * 80 + kk * 32 + (lane >> 4) * 16);
#pragma unroll
            for (int p = 0; p < 4; p++)
                ldsm4(bq[p], sB + (wn * 64 + p * 16 + (lane & 15)) * 80 + kk * 32 + (lane >> 4) * 16);
#pragma unroll
            for (int mt = 0; mt < 2; mt++)
#pragma unroll
                for (int nt = 0; nt < 8; nt++) {
                    int p = nt >> 1, j = nt & 1;
                    mma16816(acc[mt][nt], a[mt], bq[p][j], bq[p][j + 2]);
                }
        }
    }

    const int cbase = nBase + wn * 64;
#pragma unroll
    for (int nt = 0; nt < 8; nt++) {
        int col = cbase + nt * 8 + 2 * (lane & 3);
        float2 bv = *(const float2*)(bias + col);
#pragma unroll
        for (int mt = 0; mt < 2; mt++) {
            int r = mBase + wm * 32 + mt * 16 + (lane >> 2);
            float2 v0; v0.x = acc[mt][nt][0] + bv.x; v0.y = acc[mt][nt][1] + bv.y;
            float2 v1; v1.x = acc[mt][nt][2] + bv.x; v1.y = acc[mt][nt][3] + bv.y;
            *(float2*)(C + (size_t)r * N + col) = v0;
            *(float2*)(C + (size_t)(r + 8) * N + col) = v1;
        }
    }
}

// ================= flash attention v3: register-resident S/P, double-buffered K/V ========
// 8 warps: wm=wid>>1 (16 q-rows), wn=wid&1 (keys wn*32..+32 as PV k-dim).
// Each warp accumulates PARTIAL O over its 32 keys for ALL d=64; halves summed at end.
// Smem: Q[64][272B]@0 ; K stages @17408,@34816 ; V stages(128x144B) @52224,@70656 ;
//       Rm f32[128]@89088 ; Rs f32[128]@89600 ; (epilogue Ob f32[64][68] reuses @17408)
#define AT3_SMEM 90112

__global__ __launch_bounds__(256, 2)
void attn3(const __nv_bfloat16* __restrict__ Q2, const __nv_bfloat16* __restrict__ K2,
           const __nv_bfloat16* __restrict__ V2, float* __restrict__ ao) {
    extern __shared__ char sm[];
    const uint32_t sb = smem_u32(sm);
    const uint32_t Qu = sb;
    const uint32_t KuS[2] = { sb + 17408, sb + 34816 };
    const uint32_t VuS[2] = { sb + 52224, sb + 70656 };
    float* Rm = (float*)(sm + 89088);
    float* Rs = (float*)(sm + 89600);

    const int tid = threadIdx.x, wid = tid >> 5, lane = tid & 31;
    const int wm = wid >> 1, wn = wid & 1;
    const int bh = blockIdx.y;
    const int q0 = blockIdx.x * 64;
    const float scale = 0.125f;
    const int r_lo = wm * 16 + (lane >> 2);   // global row in [0,64)

    const __nv_bfloat16* Qg = Q2 + ((size_t)bh * 2048 + q0) * 128;
    const __nv_bfloat16* Kg0 = K2 + (size_t)bh * 2048 * 128;
    const __nv_bfloat16* Vg0 = V2 + (size_t)bh * 2048 * 128;

    auto loadKV = [&](int st, int kt) {
        const __nv_bfloat16* Kg = Kg0 + (size_t)kt * 64 * 128;
        const __nv_bfloat16* Vg = Vg0 + (size_t)kt * 64 * 128;
#pragma unroll
        for (int i = 0; i < 4; i++) {
            int idx = tid + i * 256;
            int row = idx >> 4, j = idx & 15;
            cp16(KuS[st] + row * 272 + j * 16, Kg + row * 128 + j * 8);
        }
#pragma unroll
        for (int i = 0; i < 4; i++) {
            int idx = tid + i * 256;
            int row = idx >> 3, j = idx & 7;
            cp16(VuS[st] + row * 144 + j * 16, Vg + (row & 63) * 128 + (row >> 6) * 64 + j * 8);
        }
    };

    // Q tile + first K/V stage
#pragma unroll
    for (int i = 0; i < 4; i++) {
        int idx = tid + i * 256;
        int row = idx >> 4, j = idx & 15;
        cp16(Qu + row * 272 + j * 16, Qg + row * 128 + j * 8);
    }
    loadKV(0, 0);
    cp_commit();

    float oc[8][4] = {};
    float mrow[2] = { -1e30f, -1e30f };
    float lrow[2] = { 0.f, 0.f };

    for (int kt = 0; kt < 32; kt++) {
        cp_wait0();
        __syncthreads();
        if (kt + 1 < 32) { loadKV((kt + 1) & 1, kt + 1); cp_commit(); }

        const uint32_t Kst = KuS[kt & 1], Vst = VuS[kt & 1];

        // ---- S = Q' @ K'^T  (rows wm*16+16, keys wn*32+32) ----
        float sc[4][4] = {};
#pragma unroll
        for (int ks = 0; ks < 12; ks++) {
            int qg = (ks & 3) + (((ks >> 2) & 1) << 2);
            int kg = (ks & 3) + ((ks >> 3) << 2);
            uint32_t aq[4], bk0[4], bk1[4];
            ldsm4(aq, Qu + (wm * 16 + (lane & 15)) * 272 + qg * 32 + (lane >> 4) * 16);
            ldsm4(bk0, Kst + (wn * 32 + (lane & 15)) * 272 + kg * 32 + (lane >> 4) * 16);
            ldsm4(bk1, Kst + (wn * 32 + 16 + (lane & 15)) * 272 + kg * 32 + (lane >> 4) * 16);
            mma16816(sc[0], aq, bk0[0], bk0[2]);
            mma16816(sc[1], aq, bk0[1], bk0[3]);
            mma16816(sc[2], aq, bk1[0], bk1[2]);
            mma16816(sc[3], aq, bk1[1], bk1[3]);
        }

        // ---- softmax on fragments ----
        // thread owns rows r_lo, r_lo+8; cols wn*32 + nt*8 + 2*(lane&3) + {0,1}
        float m0 = -1e30f, m1 = -1e30f;
#pragma unroll
        for (int nt = 0; nt < 4; nt++) {
#pragma unroll
            for (int j = 0; j < 4; j++) sc[nt][j] *= scale;
            m0 = fmaxf(m0, fmaxf(sc[nt][0], sc[nt][1]));
            m1 = fmaxf(m1, fmaxf(sc[nt][2], sc[nt][3]));
        }
        m0 = fmaxf(m0, __shfl_xor_sync(0xffffffffu, m0, 1));
        m0 = fmaxf(m0, __shfl_xor_sync(0xffffffffu, m0, 2));
        m1 = fmaxf(m1, __shfl_xor_sync(0xffffffffu, m1, 1));
        m1 = fmaxf(m1, __shfl_xor_sync(0xffffffffu, m1, 2));
        if ((lane & 3) == 0) {
            Rm[r_lo * 2 + wn] = m0;
            Rm[(r_lo + 8) * 2 + wn] = m1;
        }
        __syncthreads();
        float mn0 = fmaxf(mrow[0], fmaxf(Rm[r_lo * 2], Rm[r_lo * 2 + 1]));
        float mn1 = fmaxf(mrow[1], fmaxf(Rm[(r_lo + 8) * 2], Rm[(r_lo + 8) * 2 + 1]));
        float al0 = __expf(mrow[0] - mn0), al1 = __expf(mrow[1] - mn1);
        mrow[0] = mn0; mrow[1] = mn1;

        float s0 = 0.f, s1 = 0.f;
#pragma unroll
        for (int nt = 0; nt < 4; nt++) {
            sc[nt][0] = __expf(sc[nt][0] - mn0);
            sc[nt][1] = __expf(sc[nt][1] - mn0);
            sc[nt][2] = __expf(sc[nt][2] - mn1);
            sc[nt][3] = __expf(sc[nt][3] - mn1);
            s0 += sc[nt][0] + sc[nt][1];
            s1 += sc[nt][2] + sc[nt][3];
        }
        s0 += __shfl_xor_sync(0xffffffffu, s0, 1);
        s0 += __shfl_xor_sync(0xffffffffu, s0, 2);
        s1 += __shfl_xor_sync(0xffffffffu, s1, 1);
        s1 += __shfl_xor_sync(0xffffffffu, s1, 2);
        if ((lane & 3) == 0) {
            Rs[r_lo * 2 + wn] = s0;
            Rs[(r_lo + 8) * 2 + wn] = s1;
        }

        // rescale partial O by alpha (rows local)
#pragma unroll
        for (int nt = 0; nt < 8; nt++) {
            oc[nt][0] *= al0; oc[nt][1] *= al0;
            oc[nt][2] *= al1; oc[nt][3] *= al1;
        }
        __syncthreads();
        lrow[0] = lrow[0] * al0 + Rs[r_lo * 2] + Rs[r_lo * 2 + 1];
        lrow[1] = lrow[1] * al1 + Rs[(r_lo + 8) * 2] + Rs[(r_lo + 8) * 2 + 1];

        // ---- pack P fragments (register->register) ----
        // Ph/Pl for kg in {0,1}: keys wn*32 + kg*16 (+{0..15})
        uint32_t Ph[2][4], Pl[2][4];
#pragma unroll
        for (int kg = 0; kg < 2; kg++) {
            const float* e0 = sc[kg * 2];     // cols 2q,2q+1 of first 8 in group
            const float* e1 = sc[kg * 2 + 1]; // cols +8
            float h;
            h = __bfloat162float(__float2bfloat16(e0[0]));
            float h2 = __bfloat162float(__float2bfloat16(e0[1]));
            Ph[kg][0] = packbf(e0[0], e0[1]); Pl[kg][0] = packbf(e0[0] - h, e0[1] - h2);
            h = __bfloat162float(__float2bfloat16(e0[2]));
            h2 = __bfloat162float(__float2bfloat16(e0[3]));
            Ph[kg][1] = packbf(e0[2], e0[3]); Pl[kg][1] = packbf(e0[2] - h, e0[3] - h2);
            h = __bfloat162float(__float2bfloat16(e1[0]));
            h2 = __bfloat162float(__float2bfloat16(e1[1]));
            Ph[kg][2] = packbf(e1[0], e1[1]); Pl[kg][2] = packbf(e1[0] - h, e1[1] - h2);
            h = __bfloat162float(__float2bfloat16(e1[2]));
            h2 = __bfloat162float(__float2bfloat16(e1[3]));
            Ph[kg][3] = packbf(e1[2], e1[3]); Pl[kg][3] = packbf(e1[2] - h, e1[3] - h2);
        }

        // ---- partial O += P' @ V' over this warp's 32 keys, all d=64 ----
#pragma unroll
        for (int vt = 0; vt < 2; vt++) {          // 0: Vh rows 0-63 ; 1: Vl rows 64-127
#pragma unroll
            for (int kg = 0; kg < 2; kg++) {
                uint32_t bv[4][4];
#pragma unroll
                for (int p = 0; p < 4; p++)
                    ldsm4t(bv[p], Vst + (vt * 64 + wn * 32 + kg * 16 + (lane & 15)) * 144 +
                                   p * 32 + (lane >> 4) * 16);
#pragma unroll
                for (int p = 0; p < 4; p++)
#pragma unroll
                    for (int j = 0; j < 2; j++) {
                        mma16816(oc[p * 2 + j], Ph[kg], bv[p][j * 2], bv[p][j * 2 + 1]);
                        if (vt == 0)
                            mma16816(oc[p * 2 + j], Pl[kg], bv[p][j * 2], bv[p][j * 2 + 1]);
                    }
            }
        }
    }

    // ---- combine wn halves and store ----
    float* Ob = (float*)(sm + 17408);   // reuse K stage 0 (64 x 68 f32)
    __syncthreads();
    if (wn == 0) {
#pragma unroll
        for (int nt = 0; nt < 8; nt++) {
            int c = nt * 8 + 2 * (lane & 3);
            *(float2*)(Ob + r_lo * 68 + c) = make_float2(oc[nt][0], oc[nt][1]);
            *(float2*)(Ob + (r_lo + 8) * 68 + c) = make_float2(oc[nt][2], oc[nt][3]);
        }
    }
    __syncthreads();
    if (wn == 1) {
        int b = bh / 12, h = bh % 12;
        float i0 = 1.0f / lrow[0], i1 = 1.0f / lrow[1];
        int grow = b * 2048 + q0;
#pragma unroll
        for (int nt = 0; nt < 8; nt++) {
            int c = nt * 8 + 2 * (lane & 3);
            float2 w0 = *(float2*)(Ob + r_lo * 68 + c);
            float2 w1 = *(float2*)(Ob + (r_lo + 8) * 68 + c);
            float2 v0; v0.x = (w0.x + oc[nt][0]) * i0; v0.y = (w0.y + oc[nt][1]) * i0;
            float2 v1; v1.x = (w1.x + oc[nt][2]) * i1; v1.y = (w1.y + oc[nt][3]) * i1;
            *(float2*)(ao + (size_t)(grow + r_lo) * 768 + h * 64 + c) = v0;
            *(float2*)(ao + (size_t)(grow + r_lo + 8) * 768 + h * 64 + c) = v1;
        }
    }
}

// ---------------- launch ----------------
extern "C" void kernel_launch(void* const* d_in, const int* in_sizes, int n_in,
                              void* d_out, int out_size) {
    const float* x      = (const float*)d_in[0];
    const float* qkv_w  = (const float*)d_in[1];
    const float* qkv_b  = (const float*)d_in[2];
    const float* proj_w = (const float*)d_in[3];
    const float* proj_b = (const float*)d_in[4];
    float* out = (float*)d_out;

    float *qkv, *ao;
    __nv_bfloat16 *A2, *B1, *B2, *Q2, *K2, *V2;
    cudaGetSymbolAddress((void**)&qkv, g_qkv);
    cudaGetSymbolAddress((void**)&ao,  g_ao);
    cudaGetSymbolAddress((void**)&A2,  g_A2);
    cudaGetSymbolAddress((void**)&B1,  g_B1);
    cudaGetSymbolAddress((void**)&B2,  g_B2);
    cudaGetSymbolAddress((void**)&Q2,  g_Q2);
    cudaGetSymbolAddress((void**)&K2,  g_K2);
    cudaGetSymbolAddress((void**)&V2,  g_V2);

    const int gemm_smem = 3 * 20480;
    cudaFuncSetAttribute(mma_gemm, cudaFuncAttributeMaxDynamicSharedMemorySize, gemm_smem);
    cudaFuncSetAttribute(attn3, cudaFuncAttributeMaxDynamicSharedMemorySize, AT3_SMEM);

    split3<<<(4096 * 192 + 255) / 256, 256>>>(x, A2, 4096, 768, 1);
    split3<<<(2304 * 192 + 255) / 256, 256>>>(qkv_w, B1, 2304, 768, 0);

    mma_gemm<<<dim3(18, 32), 256, gemm_smem>>>(A2, B1, qkv_b, qkv, 4096, 2304, 2304);

    splitQKV<<<(4096 * 576 + 255) / 256, 256>>>(qkv, Q2, K2, V2);

    attn3<<<dim3(32, 24), 256, AT3_SMEM>>>(Q2, K2, V2, ao);

    split3<<<(4096 * 192 + 255) / 256, 256>>>(ao, A2, 4096, 768, 1);
    split3<<<(768 * 192 + 255) / 256, 256>>>(proj_w, B2, 768, 768, 0);

    mma_gemm<<<dim3(6, 32), 256, gemm_smem>>>(A2, B2, proj_b, out, 4096, 768, 2304);
}

// round 8
// speedup vs baseline: 2.4356x; 1.0674x over previous
#include <cuda_runtime.h>
#include <cuda_bf16.h>
#include <cstdint>

// ---------------- scratch (no cudaMalloc allowed) ----------------
__device__ float g_qkv[4096 * 2304];
__device__ float g_ao [4096 * 768];
__device__ __nv_bfloat16 g_A2[4096 * 2304];
__device__ __nv_bfloat16 g_B1[2304 * 2304];
__device__ __nv_bfloat16 g_B2[768 * 2304];
__device__ __nv_bfloat16 g_Q2[24 * 2048 * 128];
__device__ __nv_bfloat16 g_K2[24 * 2048 * 128];
__device__ __nv_bfloat16 g_V2[24 * 2048 * 128];

// ================= helpers =================
__device__ __forceinline__ uint32_t smem_u32(const void* p) {
    uint32_t a;
    asm("{ .reg .u64 t; cvta.to.shared.u64 t, %1; cvt.u32.u64 %0, t; }" : "=r"(a) : "l"(p));
    return a;
}
__device__ __forceinline__ void ldsm4(uint32_t* r, uint32_t a) {
    asm volatile("ldmatrix.sync.aligned.m8n8.x4.shared.b16 {%0,%1,%2,%3}, [%4];"
                 : "=r"(r[0]), "=r"(r[1]), "=r"(r[2]), "=r"(r[3]) : "r"(a));
}
__device__ __forceinline__ void ldsm4t(uint32_t* r, uint32_t a) {
    asm volatile("ldmatrix.sync.aligned.m8n8.x4.trans.shared.b16 {%0,%1,%2,%3}, [%4];"
                 : "=r"(r[0]), "=r"(r[1]), "=r"(r[2]), "=r"(r[3]) : "r"(a));
}
__device__ __forceinline__ void mma16816(float* d, const uint32_t* a, uint32_t b0, uint32_t b1) {
    asm volatile("mma.sync.aligned.m16n8k16.row.col.f32.bf16.bf16.f32 "
                 "{%0,%1,%2,%3},{%4,%5,%6,%7},{%8,%9},{%0,%1,%2,%3};"
                 : "+f"(d[0]), "+f"(d[1]), "+f"(d[2]), "+f"(d[3])
                 : "r"(a[0]), "r"(a[1]), "r"(a[2]), "r"(a[3]), "r"(b0), "r"(b1));
}
__device__ __forceinline__ void cp16(uint32_t saddr, const void* gaddr) {
    asm volatile("cp.async.cg.shared.global [%0], [%1], 16;" :: "r"(saddr), "l"(gaddr));
}
__device__ __forceinline__ void cp_commit() { asm volatile("cp.async.commit_group;" ::: "memory"); }
__device__ __forceinline__ void cp_wait1()  { asm volatile("cp.async.wait_group 1;" ::: "memory"); }
__device__ __forceinline__ void cp_wait0()  { asm volatile("cp.async.wait_group 0;" ::: "memory"); }

__device__ __forceinline__ void split2(float x, float y, __nv_bfloat162& hi, __nv_bfloat162& lo) {
    __nv_bfloat16 hx = __float2bfloat16(x), hy = __float2bfloat16(y);
    hi.x = hx; hi.y = hy;
    lo.x = __float2bfloat16(x - __bfloat162float(hx));
    lo.y = __float2bfloat16(y - __bfloat162float(hy));
}
__device__ __forceinline__ uint32_t packbf(float x, float y) {
    __nv_bfloat162 h; h.x = __float2bfloat16(x); h.y = __float2bfloat16(y);
    return *(uint32_t*)&h;
}

// ===== split-concat for GEMM operands =====
__global__ void split3(const float* __restrict__ in, __nv_bfloat16* __restrict__ out,
                       int R, int K, int loMid) {
    int i = blockIdx.x * blockDim.x + threadIdx.x;
    int per_row = K >> 2;
    if (i >= R * per_row) return;
    int r = i / per_row, f = i % per_row;
    float4 v = *(const float4*)(in + (size_t)r * K + f * 4);
    __nv_bfloat162 H0, H1, L0, L1;
    split2(v.x, v.y, H0, L0);
    split2(v.z, v.w, H1, L1);
    __nv_bfloat16* o = out + (size_t)r * 3 * K + f * 4;
    ((__nv_bfloat162*)o)[0] = H0;  ((__nv_bfloat162*)o)[1] = H1;
    if (loMid) {
        ((__nv_bfloat162*)(o + K))[0] = L0;     ((__nv_bfloat162*)(o + K))[1] = L1;
        ((__nv_bfloat162*)(o + 2 * K))[0] = H0; ((__nv_bfloat162*)(o + 2 * K))[1] = H1;
    } else {
        ((__nv_bfloat162*)(o + K))[0] = H0;     ((__nv_bfloat162*)(o + K))[1] = H1;
        ((__nv_bfloat162*)(o + 2 * K))[0] = L0; ((__nv_bfloat162*)(o + 2 * K))[1] = L1;
    }
}

// ===== per-head split: qkv f32 -> Q2/K2/V2 [24][2048][128] bf16 (hi|lo) =====
__global__ void splitQKV(const float* __restrict__ qkv,
                         __nv_bfloat16* __restrict__ Q2, __nv_bfloat16* __restrict__ K2,
                         __nv_bfloat16* __restrict__ V2) {
    int i = blockIdx.x * blockDim.x + threadIdx.x;
    if (i >= 4096 * 576) return;
    int row = i / 576, c4 = i % 576;
    int col = c4 * 4;
    int m = col / 768;
    int hc = col - m * 768;
    int h = hc >> 6, d = hc & 63;
    float4 v = *(const float4*)(qkv + (size_t)row * 2304 + col);
    __nv_bfloat162 H0, H1, L0, L1;
    split2(v.x, v.y, H0, L0);
    split2(v.z, v.w, H1, L1);
    __nv_bfloat16* base = (m == 0 ? Q2 : m == 1 ? K2 : V2);
    __nv_bfloat16* dst = base + ((size_t)((row >> 11) * 12 + h) * 2048 + (row & 2047)) * 128 + d;
    ((__nv_bfloat162*)dst)[0] = H0;        ((__nv_bfloat162*)dst)[1] = H1;
    ((__nv_bfloat162*)(dst + 64))[0] = L0; ((__nv_bfloat162*)(dst + 64))[1] = L1;
}

// ================= bf16 GEMM (validated R5) =================
__global__ __launch_bounds__(256, 2)
void mma_gemm(const __nv_bfloat16* __restrict__ A, const __nv_bfloat16* __restrict__ B,
              const float* __restrict__ bias, float* __restrict__ C,
              int M, int N, int K3) {
    extern __shared__ char sm[];
    const uint32_t sb = smem_u32(sm);
    const int tid = threadIdx.x, wid = tid >> 5, lane = tid & 31;
    const int wm = wid & 3, wn = wid >> 2;
    const int mBase = blockIdx.y * 128, nBase = blockIdx.x * 128;
    const int NIT = K3 / 32;

    float acc[2][8][4] = {};

    auto load_stage = [&](int st, int k0) {
        uint32_t sA = sb + st * 20480, sB = sA + 10240;
#pragma unroll
        for (int i2 = 0; i2 < 2; i2++) {
            int c = tid + i2 * 256;
            int row = c >> 2, kc = c & 3;
            cp16(sA + row * 80 + kc * 16, A + (size_t)(mBase + row) * K3 + k0 + kc * 8);
            cp16(sB + row * 80 + kc * 16, B + (size_t)(nBase + row) * K3 + k0 + kc * 8);
        }
    };

    load_stage(0, 0);  cp_commit();
    load_stage(1, 32); cp_commit();

    for (int it = 0; it < NIT; it++) {
        cp_wait1();
        __syncthreads();
        if (it + 2 < NIT) load_stage((it + 2) % 3, (it + 2) * 32);
        cp_commit();

        uint32_t sA = sb + (it % 3) * 20480, sB = sA + 10240;
#pragma unroll
        for (int kk = 0; kk < 2; kk++) {
            uint32_t a[2][4], bq[4][4];
#pragma unroll
            for (int mt = 0; mt < 2; mt++)
                ldsm4(a[mt], sA + (wm * 32 + mt * 16 + (lane & 15)) * 80 + kk * 32 + (lane >> 4) * 16);
#pragma unroll
            for (int p = 0; p < 4; p++)
                ldsm4(bq[p], sB + (wn * 64 + p * 16 + (lane & 15)) * 80 + kk * 32 + (lane >> 4) * 16);
#pragma unroll
            for (int mt = 0; mt < 2; mt++)
#pragma unroll
                for (int nt = 0; nt < 8; nt++) {
                    int p = nt >> 1, j = nt & 1;
                    mma16816(acc[mt][nt], a[mt], bq[p][j], bq[p][j + 2]);
                }
        }
    }

    const int cbase = nBase + wn * 64;
#pragma unroll
    for (int nt = 0; nt < 8; nt++) {
        int col = cbase + nt * 8 + 2 * (lane & 3);
        float2 bv = *(const float2*)(bias + col);
#pragma unroll
        for (int mt = 0; mt < 2; mt++) {
            int r = mBase + wm * 32 + mt * 16 + (lane >> 2);
            float2 v0; v0.x = acc[mt][nt][0] + bv.x; v0.y = acc[mt][nt][1] + bv.y;
            float2 v1; v1.x = acc[mt][nt][2] + bv.x; v1.y = acc[mt][nt][3] + bv.y;
            *(float2*)(C + (size_t)r * N + col) = v0;
            *(float2*)(C + (size_t)(r + 8) * N + col) = v1;
        }
    }
}

// ================= flash attention v4: warp-autonomous rows, 1 sync/iter =================
// 8 warps; warp owns rows wid*16..+16 of a 128-row q-tile and ALL 32 keys of the kv tile.
// Softmax entirely quad-shfl local; K/V double-buffered; epilogue warp-local.
// Smem: Q[128][272B]@0(34816) ; K stages 32x272B @34816,@43520 ;
//       V stages 64x144B(Vh rows0-31,Vl 32-63) @52224,@61440 ; total 70656.
#define AT4_SMEM 70656

__global__ __launch_bounds__(256, 2)
void attn4(const __nv_bfloat16* __restrict__ Q2, const __nv_bfloat16* __restrict__ K2,
           const __nv_bfloat16* __restrict__ V2, float* __restrict__ ao) {
    extern __shared__ char sm[];
    const uint32_t sb = smem_u32(sm);
    const uint32_t Qu = sb;
    const uint32_t KuS[2] = { sb + 34816, sb + 43520 };
    const uint32_t VuS[2] = { sb + 52224, sb + 61440 };

    const int tid = threadIdx.x, wid = tid >> 5, lane = tid & 31;
    const int bh = blockIdx.y;
    const int q0 = blockIdx.x * 128;
    const float scale = 0.125f;

    const __nv_bfloat16* Qg = Q2 + ((size_t)bh * 2048 + q0) * 128;
    const __nv_bfloat16* Kg0 = K2 + (size_t)bh * 2048 * 128;
    const __nv_bfloat16* Vg0 = V2 + (size_t)bh * 2048 * 128;

    auto loadKV = [&](int st, int kt) {
        const __nv_bfloat16* Kg = Kg0 + (size_t)kt * 32 * 128;
        const __nv_bfloat16* Vg = Vg0 + (size_t)kt * 32 * 128;
#pragma unroll
        for (int i = 0; i < 2; i++) {
            int idx = tid + i * 256;            // 512 chunks: K 32 rows x 16
            int row = idx >> 4, j = idx & 15;
            cp16(KuS[st] + row * 272 + j * 16, Kg + row * 128 + j * 8);
        }
#pragma unroll
        for (int i = 0; i < 2; i++) {
            int idx = tid + i * 256;            // 512 chunks: V 64 rows x 8
            int row = idx >> 3, j = idx & 7;    // row: key|half
            cp16(VuS[st] + row * 144 + j * 16,
                 Vg + (row & 31) * 128 + (row >> 5) * 64 + j * 8);
        }
    };

    // Q tile (128 rows x 17 chunks? no: 16 chunks) + first K/V stage
#pragma unroll
    for (int i = 0; i < 8; i++) {
        int idx = tid + i * 256;                // 2048 chunks: Q 128 rows x 16
        int row = idx >> 4, j = idx & 15;
        cp16(Qu + row * 272 + j * 16, Qg + row * 128 + j * 8);
    }
    loadKV(0, 0);
    cp_commit();

    float oc[8][4] = {};
    float mrow[2] = { -1e30f, -1e30f };
    float lrow[2] = { 0.f, 0.f };

    for (int kt = 0; kt < 64; kt++) {
        cp_wait0();
        __syncthreads();
        if (kt + 1 < 64) { loadKV((kt + 1) & 1, kt + 1); cp_commit(); }

        const uint32_t Kst = KuS[kt & 1], Vst = VuS[kt & 1];

        // ---- S = Q' @ K'^T : rows wid*16+16, keys 0..31 ----
        float sc[4][4] = {};
#pragma unroll
        for (int ks = 0; ks < 12; ks++) {
            int qg = (ks & 3) + (((ks >> 2) & 1) << 2);
            int kg = (ks & 3) + ((ks >> 3) << 2);
            uint32_t aq[4], bk0[4], bk1[4];
            ldsm4(aq, Qu + (wid * 16 + (lane & 15)) * 272 + qg * 32 + (lane >> 4) * 16);
            ldsm4(bk0, Kst + (lane & 15) * 272 + kg * 32 + (lane >> 4) * 16);
            ldsm4(bk1, Kst + (16 + (lane & 15)) * 272 + kg * 32 + (lane >> 4) * 16);
            mma16816(sc[0], aq, bk0[0], bk0[2]);
            mma16816(sc[1], aq, bk0[1], bk0[3]);
            mma16816(sc[2], aq, bk1[0], bk1[2]);
            mma16816(sc[3], aq, bk1[1], bk1[3]);
        }

        // ---- warp-local online softmax (quad shfl only) ----
        float m0 = -1e30f, m1 = -1e30f;
#pragma unroll
        for (int nt = 0; nt < 4; nt++) {
#pragma unroll
            for (int j = 0; j < 4; j++) sc[nt][j] *= scale;
            m0 = fmaxf(m0, fmaxf(sc[nt][0], sc[nt][1]));
            m1 = fmaxf(m1, fmaxf(sc[nt][2], sc[nt][3]));
        }
        m0 = fmaxf(m0, __shfl_xor_sync(0xffffffffu, m0, 1));
        m0 = fmaxf(m0, __shfl_xor_sync(0xffffffffu, m0, 2));
        m1 = fmaxf(m1, __shfl_xor_sync(0xffffffffu, m1, 1));
        m1 = fmaxf(m1, __shfl_xor_sync(0xffffffffu, m1, 2));
        float mn0 = fmaxf(mrow[0], m0), mn1 = fmaxf(mrow[1], m1);
        float al0 = __expf(mrow[0] - mn0), al1 = __expf(mrow[1] - mn1);
        mrow[0] = mn0; mrow[1] = mn1;

        float s0 = 0.f, s1 = 0.f;
#pragma unroll
        for (int nt = 0; nt < 4; nt++) {
            sc[nt][0] = __expf(sc[nt][0] - mn0);
            sc[nt][1] = __expf(sc[nt][1] - mn0);
            sc[nt][2] = __expf(sc[nt][2] - mn1);
            sc[nt][3] = __expf(sc[nt][3] - mn1);
            s0 += sc[nt][0] + sc[nt][1];
            s1 += sc[nt][2] + sc[nt][3];
        }
        s0 += __shfl_xor_sync(0xffffffffu, s0, 1);
        s0 += __shfl_xor_sync(0xffffffffu, s0, 2);
        s1 += __shfl_xor_sync(0xffffffffu, s1, 1);
        s1 += __shfl_xor_sync(0xffffffffu, s1, 2);
        lrow[0] = lrow[0] * al0 + s0;
        lrow[1] = lrow[1] * al1 + s1;

#pragma unroll
        for (int nt = 0; nt < 8; nt++) {
            oc[nt][0] *= al0; oc[nt][1] *= al0;
            oc[nt][2] *= al1; oc[nt][3] *= al1;
        }

        // ---- pack P (hi + residual lo) ----
        uint32_t Ph[2][4], Pl[2][4];
#pragma unroll
        for (int kg = 0; kg < 2; kg++) {
            const float* e0 = sc[kg * 2];
            const float* e1 = sc[kg * 2 + 1];
            float h, h2;
            h = __bfloat162float(__float2bfloat16(e0[0]));
            h2 = __bfloat162float(__float2bfloat16(e0[1]));
            Ph[kg][0] = packbf(e0[0], e0[1]); Pl[kg][0] = packbf(e0[0] - h, e0[1] - h2);
            h = __bfloat162float(__float2bfloat16(e0[2]));
            h2 = __bfloat162float(__float2bfloat16(e0[3]));
            Ph[kg][1] = packbf(e0[2], e0[3]); Pl[kg][1] = packbf(e0[2] - h, e0[3] - h2);
            h = __bfloat162float(__float2bfloat16(e1[0]));
            h2 = __bfloat162float(__float2bfloat16(e1[1]));
            Ph[kg][2] = packbf(e1[0], e1[1]); Pl[kg][2] = packbf(e1[0] - h, e1[1] - h2);
            h = __bfloat162float(__float2bfloat16(e1[2]));
            h2 = __bfloat162float(__float2bfloat16(e1[3]));
            Ph[kg][3] = packbf(e1[2], e1[3]); Pl[kg][3] = packbf(e1[2] - h, e1[3] - h2);
        }

        // ---- O += P' @ V' over 32 keys, all d=64 ----
#pragma unroll
        for (int vt = 0; vt < 2; vt++) {          // 0: Vh rows 0-31 ; 1: Vl rows 32-63
#pragma unroll
            for (int kg = 0; kg < 2; kg++) {
                uint32_t bv[4][4];
#pragma unroll
                for (int p = 0; p < 4; p++)
                    ldsm4t(bv[p], Vst + (vt * 32 + kg * 16 + (lane & 15)) * 144 +
                                   p * 32 + (lane >> 4) * 16);
#pragma unroll
                for (int p = 0; p < 4; p++)
#pragma unroll
                    for (int j = 0; j < 2; j++) {
                        mma16816(oc[p * 2 + j], Ph[kg], bv[p][j * 2], bv[p][j * 2 + 1]);
                        if (vt == 0)
                            mma16816(oc[p * 2 + j], Pl[kg], bv[p][j * 2], bv[p][j * 2 + 1]);
                    }
            }
        }
    }

    // ---- warp-local epilogue ----
    {
        int b = bh / 12, h = bh % 12;
        float i0 = 1.0f / lrow[0], i1 = 1.0f / lrow[1];
        int r = q0 + wid * 16 + (lane >> 2);
        int grow = b * 2048 + r;
#pragma unroll
        for (int nt = 0; nt < 8; nt++) {
            int c = h * 64 + nt * 8 + 2 * (lane & 3);
            float2 v0; v0.x = oc[nt][0] * i0; v0.y = oc[nt][1] * i0;
            float2 v1; v1.x = oc[nt][2] * i1; v1.y = oc[nt][3] * i1;
            *(float2*)(ao + (size_t)grow * 768 + c) = v0;
            *(float2*)(ao + (size_t)(grow + 8) * 768 + c) = v1;
        }
    }
}

// ---------------- launch ----------------
extern "C" void kernel_launch(void* const* d_in, const int* in_sizes, int n_in,
                              void* d_out, int out_size) {
    const float* x      = (const float*)d_in[0];
    const float* qkv_w  = (const float*)d_in[1];
    const float* qkv_b  = (const float*)d_in[2];
    const float* proj_w = (const float*)d_in[3];
    const float* proj_b = (const float*)d_in[4];
    float* out = (float*)d_out;

    float *qkv, *ao;
    __nv_bfloat16 *A2, *B1, *B2, *Q2, *K2, *V2;
    cudaGetSymbolAddress((void**)&qkv, g_qkv);
    cudaGetSymbolAddress((void**)&ao,  g_ao);
    cudaGetSymbolAddress((void**)&A2,  g_A2);
    cudaGetSymbolAddress((void**)&B1,  g_B1);
    cudaGetSymbolAddress((void**)&B2,  g_B2);
    cudaGetSymbolAddress((void**)&Q2,  g_Q2);
    cudaGetSymbolAddress((void**)&K2,  g_K2);
    cudaGetSymbolAddress((void**)&V2,  g_V2);

    const int gemm_smem = 3 * 20480;
    cudaFuncSetAttribute(mma_gemm, cudaFuncAttributeMaxDynamicSharedMemorySize, gemm_smem);
    cudaFuncSetAttribute(attn4, cudaFuncAttributeMaxDynamicSharedMemorySize, AT4_SMEM);

    split3<<<(4096 * 192 + 255) / 256, 256>>>(x, A2, 4096, 768, 1);
    split3<<<(2304 * 192 + 255) / 256, 256>>>(qkv_w, B1, 2304, 768, 0);

    mma_gemm<<<dim3(18, 32), 256, gemm_smem>>>(A2, B1, qkv_b, qkv, 4096, 2304, 2304);

    splitQKV<<<(4096 * 576 + 255) / 256, 256>>>(qkv, Q2, K2, V2);

    attn4<<<dim3(16, 24), 256, AT4_SMEM>>>(Q2, K2, V2, ao);

    split3<<<(4096 * 192 + 255) / 256, 256>>>(ao, A2, 4096, 768, 1);
    split3<<<(768 * 192 + 255) / 256, 256>>>(proj_w, B2, 768, 768, 0);

    mma_gemm<<<dim3(6, 32), 256, gemm_smem>>>(A2, B2, proj_b, out, 4096, 768, 2304);
}

// round 9
// speedup vs baseline: 2.4949x; 1.0243x over previous
#include <cuda_runtime.h>
#include <cuda_bf16.h>
#include <cstdint>

// ---------------- scratch (no cudaMalloc allowed) ----------------
__device__ __nv_bfloat16 g_A2[4096 * 2304];          // x-split, later ao-split [hi|lo|hi]
__device__ __nv_bfloat16 g_B1[2304 * 2304];          // qkv_w split [hi|hi|lo]
__device__ __nv_bfloat16 g_B2[768 * 2304];           // proj_w split [hi|hi|lo]
__device__ __nv_bfloat16 g_Q2[24 * 2048 * 128];      // per-head hi|lo
__device__ __nv_bfloat16 g_K2[24 * 2048 * 128];
__device__ __nv_bfloat16 g_V2[24 * 2048 * 128];

// ================= helpers =================
__device__ __forceinline__ uint32_t smem_u32(const void* p) {
    uint32_t a;
    asm("{ .reg .u64 t; cvta.to.shared.u64 t, %1; cvt.u32.u64 %0, t; }" : "=r"(a) : "l"(p));
    return a;
}
__device__ __forceinline__ void ldsm4(uint32_t* r, uint32_t a) {
    asm volatile("ldmatrix.sync.aligned.m8n8.x4.shared.b16 {%0,%1,%2,%3}, [%4];"
                 : "=r"(r[0]), "=r"(r[1]), "=r"(r[2]), "=r"(r[3]) : "r"(a));
}
__device__ __forceinline__ void ldsm4t(uint32_t* r, uint32_t a) {
    asm volatile("ldmatrix.sync.aligned.m8n8.x4.trans.shared.b16 {%0,%1,%2,%3}, [%4];"
                 : "=r"(r[0]), "=r"(r[1]), "=r"(r[2]), "=r"(r[3]) : "r"(a));
}
__device__ __forceinline__ void mma16816(float* d, const uint32_t* a, uint32_t b0, uint32_t b1) {
    asm volatile("mma.sync.aligned.m16n8k16.row.col.f32.bf16.bf16.f32 "
                 "{%0,%1,%2,%3},{%4,%5,%6,%7},{%8,%9},{%0,%1,%2,%3};"
                 : "+f"(d[0]), "+f"(d[1]), "+f"(d[2]), "+f"(d[3])
                 : "r"(a[0]), "r"(a[1]), "r"(a[2]), "r"(a[3]), "r"(b0), "r"(b1));
}
__device__ __forceinline__ void cp16(uint32_t saddr, const void* gaddr) {
    asm volatile("cp.async.cg.shared.global [%0], [%1], 16;" :: "r"(saddr), "l"(gaddr));
}
__device__ __forceinline__ void cp_commit() { asm volatile("cp.async.commit_group;" ::: "memory"); }
__device__ __forceinline__ void cp_wait2()  { asm volatile("cp.async.wait_group 2;" ::: "memory"); }
__device__ __forceinline__ void cp_wait0()  { asm volatile("cp.async.wait_group 0;" ::: "memory"); }

__device__ __forceinline__ void split2(float x, float y, __nv_bfloat162& hi, __nv_bfloat162& lo) {
    hi = __float22bfloat162_rn(make_float2(x, y));
    float2 b = __bfloat1622float2(hi);
    lo = __float22bfloat162_rn(make_float2(x - b.x, y - b.y));
}

// ===== split-concat: f32 -> [R][3K] bf16 (GEMM operands) =====
__global__ void split3(const float* __restrict__ in, __nv_bfloat16* __restrict__ out,
                       int R, int K, int loMid) {
    int i = blockIdx.x * blockDim.x + threadIdx.x;
    int per_row = K >> 2;
    if (i >= R * per_row) return;
    int r = i / per_row, f = i % per_row;
    float4 v = *(const float4*)(in + (size_t)r * K + f * 4);
    __nv_bfloat162 H0, H1, L0, L1;
    split2(v.x, v.y, H0, L0);
    split2(v.z, v.w, H1, L1);
    __nv_bfloat16* o = out + (size_t)r * 3 * K + f * 4;
    ((__nv_bfloat162*)o)[0] = H0;  ((__nv_bfloat162*)o)[1] = H1;
    if (loMid) {
        ((__nv_bfloat162*)(o + K))[0] = L0;     ((__nv_bfloat162*)(o + K))[1] = L1;
        ((__nv_bfloat162*)(o + 2 * K))[0] = H0; ((__nv_bfloat162*)(o + 2 * K))[1] = H1;
    } else {
        ((__nv_bfloat162*)(o + K))[0] = H0;     ((__nv_bfloat162*)(o + K))[1] = H1;
        ((__nv_bfloat162*)(o + 2 * K))[0] = L0; ((__nv_bfloat162*)(o + 2 * K))[1] = L1;
    }
}

// ================= bf16 GEMM, 4-stage; optional fused per-head split output ============
// splitOut=1: instead of fp32 C, write bf16 hi/lo per-head Q2/K2/V2 (N must be 2304).
__global__ __launch_bounds__(256, 2)
void mma_gemm(const __nv_bfloat16* __restrict__ A, const __nv_bfloat16* __restrict__ B,
              const float* __restrict__ bias, float* __restrict__ C,
              __nv_bfloat16* __restrict__ Q2o, __nv_bfloat16* __restrict__ K2o,
              __nv_bfloat16* __restrict__ V2o, int splitOut,
              int M, int N, int K3) {
    extern __shared__ char sm[];
    const uint32_t sb = smem_u32(sm);
    const int tid = threadIdx.x, wid = tid >> 5, lane = tid & 31;
    const int wm = wid & 3, wn = wid >> 2;
    const int mBase = blockIdx.y * 128, nBase = blockIdx.x * 128;
    const int NIT = K3 / 32;

    float acc[2][8][4] = {};

    auto load_stage = [&](int st, int k0) {
        uint32_t sA = sb + st * 20480, sB = sA + 10240;
#pragma unroll
        for (int i2 = 0; i2 < 2; i2++) {
            int c = tid + i2 * 256;
            int row = c >> 2, kc = c & 3;
            cp16(sA + row * 80 + kc * 16, A + (size_t)(mBase + row) * K3 + k0 + kc * 8);
            cp16(sB + row * 80 + kc * 16, B + (size_t)(nBase + row) * K3 + k0 + kc * 8);
        }
    };

    load_stage(0, 0);  cp_commit();
    load_stage(1, 32); cp_commit();
    load_stage(2, 64); cp_commit();

    for (int it = 0; it < NIT; it++) {
        cp_wait2();
        __syncthreads();
        if (it + 3 < NIT) { load_stage((it + 3) & 3, (it + 3) * 32); }
        cp_commit();

        uint32_t sA = sb + (it & 3) * 20480, sB = sA + 10240;
#pragma unroll
        for (int kk = 0; kk < 2; kk++) {
            uint32_t a[2][4], bq[4][4];
#pragma unroll
            for (int mt = 0; mt < 2; mt++)
                ldsm4(a[mt], sA + (wm * 32 + mt * 16 + (lane & 15)) * 80 + kk * 32 + (lane >> 4) * 16);
#pragma unroll
            for (int p = 0; p < 4; p++)
                ldsm4(bq[p], sB + (wn * 64 + p * 16 + (lane & 15)) * 80 + kk * 32 + (lane >> 4) * 16);
#pragma unroll
            for (int mt = 0; mt < 2; mt++)
#pragma unroll
                for (int nt = 0; nt < 8; nt++) {
                    int p = nt >> 1, j = nt & 1;
                    mma16816(acc[mt][nt], a[mt], bq[p][j], bq[p][j + 2]);
                }
        }
    }

    const int cbase = nBase + wn * 64;
#pragma unroll
    for (int nt = 0; nt < 8; nt++) {
        int col = cbase + nt * 8 + 2 * (lane & 3);
        float2 bv = *(const float2*)(bias + col);
#pragma unroll
        for (int mt = 0; mt < 2; mt++) {
            int r0 = mBase + wm * 32 + mt * 16 + (lane >> 2);
            float2 v0; v0.x = acc[mt][nt][0] + bv.x; v0.y = acc[mt][nt][1] + bv.y;
            float2 v1; v1.x = acc[mt][nt][2] + bv.x; v1.y = acc[mt][nt][3] + bv.y;
            if (!splitOut) {
                *(float2*)(C + (size_t)r0 * N + col) = v0;
                *(float2*)(C + (size_t)(r0 + 8) * N + col) = v1;
            } else {
                int m = col / 768;
                int hc = col - m * 768;
                int h = hc >> 6, d = hc & 63;
                __nv_bfloat16* base = (m == 0 ? Q2o : m == 1 ? K2o : V2o);
                __nv_bfloat162 H, L;
#pragma unroll
                for (int rr = 0; rr < 2; rr++) {
                    int r = r0 + rr * 8;
                    float2 v = rr ? v1 : v0;
                    split2(v.x, v.y, H, L);
                    __nv_bfloat16* dst = base +
                        ((size_t)((r >> 11) * 12 + h) * 2048 + (r & 2047)) * 128 + d;
                    *(__nv_bfloat162*)dst = H;
                    *(__nv_bfloat162*)(dst + 64) = L;
                }
            }
        }
    }
}

// ================= flash attention v5 =================
// warp owns 16 q-rows x 32 keys; Kh fragments reused (Qh,Ql); epilogue -> A2 [hi|lo|hi].
#define AT5_SMEM 70656

__global__ __launch_bounds__(256, 2)
void attn5(const __nv_bfloat16* __restrict__ Q2, const __nv_bfloat16* __restrict__ K2,
           const __nv_bfloat16* __restrict__ V2, __nv_bfloat16* __restrict__ A2) {
    extern __shared__ char sm[];
    const uint32_t sb = smem_u32(sm);
    const uint32_t Qu = sb;
    const uint32_t KuS[2] = { sb + 34816, sb + 43520 };
    const uint32_t VuS[2] = { sb + 52224, sb + 61440 };

    const int tid = threadIdx.x, wid = tid >> 5, lane = tid & 31;
    const int bh = blockIdx.y;
    const int q0 = blockIdx.x * 128;
    const float scale = 0.125f;

    const __nv_bfloat16* Qg = Q2 + ((size_t)bh * 2048 + q0) * 128;
    const __nv_bfloat16* Kg0 = K2 + (size_t)bh * 2048 * 128;
    const __nv_bfloat16* Vg0 = V2 + (size_t)bh * 2048 * 128;

    auto loadKV = [&](int st, int kt) {
        const __nv_bfloat16* Kg = Kg0 + (size_t)kt * 32 * 128;
        const __nv_bfloat16* Vg = Vg0 + (size_t)kt * 32 * 128;
#pragma unroll
        for (int i = 0; i < 2; i++) {
            int idx = tid + i * 256;
            int row = idx >> 4, j = idx & 15;
            cp16(KuS[st] + row * 272 + j * 16, Kg + row * 128 + j * 8);
        }
#pragma unroll
        for (int i = 0; i < 2; i++) {
            int idx = tid + i * 256;
            int row = idx >> 3, j = idx & 7;
            cp16(VuS[st] + row * 144 + j * 16,
                 Vg + (row & 31) * 128 + (row >> 5) * 64 + j * 8);
        }
    };

#pragma unroll
    for (int i = 0; i < 8; i++) {
        int idx = tid + i * 256;
        int row = idx >> 4, j = idx & 15;
        cp16(Qu + row * 272 + j * 16, Qg + row * 128 + j * 8);
    }
    loadKV(0, 0);
    cp_commit();

    float oc[8][4] = {};
    float mrow[2] = { -1e30f, -1e30f };
    float lrow[2] = { 0.f, 0.f };

    for (int kt = 0; kt < 64; kt++) {
        cp_wait0();
        __syncthreads();
        if (kt + 1 < 64) { loadKV((kt + 1) & 1, kt + 1); cp_commit(); }

        const uint32_t Kst = KuS[kt & 1], Vst = VuS[kt & 1];

        // ---- S = Qh.Kh + Ql.Kh + Qh.Kl (Kh fragments reused) ----
        float sc[4][4] = {};
#pragma unroll
        for (int g = 0; g < 4; g++) {
            const uint32_t qrow = Qu + (wid * 16 + (lane & 15)) * 272 + g * 32 + (lane >> 4) * 16;
            const uint32_t krow0 = Kst + (lane & 15) * 272 + g * 32 + (lane >> 4) * 16;
            const uint32_t krow1 = Kst + (16 + (lane & 15)) * 272 + g * 32 + (lane >> 4) * 16;
            uint32_t aqh[4], aql[4], bh0[4], bh1[4], bl0[4], bl1[4];
            ldsm4(aqh, qrow);
            ldsm4(aql, qrow + 128);
            ldsm4(bh0, krow0);
            ldsm4(bh1, krow1);
            ldsm4(bl0, krow0 + 128);
            ldsm4(bl1, krow1 + 128);
            mma16816(sc[0], aqh, bh0[0], bh0[2]); mma16816(sc[1], aqh, bh0[1], bh0[3]);
            mma16816(sc[2], aqh, bh1[0], bh1[2]); mma16816(sc[3], aqh, bh1[1], bh1[3]);
            mma16816(sc[0], aql, bh0[0], bh0[2]); mma16816(sc[1], aql, bh0[1], bh0[3]);
            mma16816(sc[2], aql, bh1[0], bh1[2]); mma16816(sc[3], aql, bh1[1], bh1[3]);
            mma16816(sc[0], aqh, bl0[0], bl0[2]); mma16816(sc[1], aqh, bl0[1], bl0[3]);
            mma16816(sc[2], aqh, bl1[0], bl1[2]); mma16816(sc[3], aqh, bl1[1], bl1[3]);
        }

        // ---- warp-local online softmax ----
        float m0 = -1e30f, m1 = -1e30f;
#pragma unroll
        for (int nt = 0; nt < 4; nt++) {
#pragma unroll
            for (int j = 0; j < 4; j++) sc[nt][j] *= scale;
            m0 = fmaxf(m0, fmaxf(sc[nt][0], sc[nt][1]));
            m1 = fmaxf(m1, fmaxf(sc[nt][2], sc[nt][3]));
        }
        m0 = fmaxf(m0, __shfl_xor_sync(0xffffffffu, m0, 1));
        m0 = fmaxf(m0, __shfl_xor_sync(0xffffffffu, m0, 2));
        m1 = fmaxf(m1, __shfl_xor_sync(0xffffffffu, m1, 1));
        m1 = fmaxf(m1, __shfl_xor_sync(0xffffffffu, m1, 2));
        float mn0 = fmaxf(mrow[0], m0), mn1 = fmaxf(mrow[1], m1);
        float al0 = __expf(mrow[0] - mn0), al1 = __expf(mrow[1] - mn1);
        mrow[0] = mn0; mrow[1] = mn1;

        float s0 = 0.f, s1 = 0.f;
#pragma unroll
        for (int nt = 0; nt < 4; nt++) {
            sc[nt][0] = __expf(sc[nt][0] - mn0);
            sc[nt][1] = __expf(sc[nt][1] - mn0);
            sc[nt][2] = __expf(sc[nt][2] - mn1);
            sc[nt][3] = __expf(sc[nt][3] - mn1);
            s0 += sc[nt][0] + sc[nt][1];
            s1 += sc[nt][2] + sc[nt][3];
        }
        s0 += __shfl_xor_sync(0xffffffffu, s0, 1);
        s0 += __shfl_xor_sync(0xffffffffu, s0, 2);
        s1 += __shfl_xor_sync(0xffffffffu, s1, 1);
        s1 += __shfl_xor_sync(0xffffffffu, s1, 2);
        lrow[0] = lrow[0] * al0 + s0;
        lrow[1] = lrow[1] * al1 + s1;

#pragma unroll
        for (int nt = 0; nt < 8; nt++) {
            oc[nt][0] *= al0; oc[nt][1] *= al0;
            oc[nt][2] *= al1; oc[nt][3] *= al1;
        }

        // ---- pack P (hi + residual) with bf162 intrinsics ----
        uint32_t Ph[2][4], Pl[2][4];
#pragma unroll
        for (int kg = 0; kg < 2; kg++) {
#pragma unroll
            for (int e = 0; e < 2; e++) {       // e=0: rows lo (c0,c1); e=1: rows hi (c2,c3)
                const float* f0 = sc[kg * 2];
                const float* f1 = sc[kg * 2 + 1];
                __nv_bfloat162 H, L;
                split2(f0[e * 2], f0[e * 2 + 1], H, L);
                Ph[kg][e] = *(uint32_t*)&H; Pl[kg][e] = *(uint32_t*)&L;
                split2(f1[e * 2], f1[e * 2 + 1], H, L);
                Ph[kg][e + 2] = *(uint32_t*)&H; Pl[kg][e + 2] = *(uint32_t*)&L;
            }
        }

        // ---- O += Ph.Vh + Pl.Vh + Ph.Vl ----
#pragma unroll
        for (int vt = 0; vt < 2; vt++) {
#pragma unroll
            for (int kg = 0; kg < 2; kg++) {
                uint32_t bv[4][4];
#pragma unroll
                for (int p = 0; p < 4; p++)
                    ldsm4t(bv[p], Vst + (vt * 32 + kg * 16 + (lane & 15)) * 144 +
                                   p * 32 + (lane >> 4) * 16);
#pragma unroll
                for (int p = 0; p < 4; p++)
#pragma unroll
                    for (int j = 0; j < 2; j++) {
                        mma16816(oc[p * 2 + j], Ph[kg], bv[p][j * 2], bv[p][j * 2 + 1]);
                        if (vt == 0)
                            mma16816(oc[p * 2 + j], Pl[kg], bv[p][j * 2], bv[p][j * 2 + 1]);
                    }
            }
        }
    }

    // ---- epilogue: write split [hi|lo|hi] rows of A2 directly ----
    {
        int b = bh / 12, h = bh % 12;
        float i0 = 1.0f / lrow[0], i1 = 1.0f / lrow[1];
        int r = b * 2048 + q0 + wid * 16 + (lane >> 2);
#pragma unroll
        for (int nt = 0; nt < 8; nt++) {
            int c = h * 64 + nt * 8 + 2 * (lane & 3);
            __nv_bfloat162 H, L;
            split2(oc[nt][0] * i0, oc[nt][1] * i0, H, L);
            __nv_bfloat16* base = A2 + (size_t)r * 2304 + c;
            *(__nv_bfloat162*)base = H;
            *(__nv_bfloat162*)(base + 768) = L;
            *(__nv_bfloat162*)(base + 1536) = H;
            split2(oc[nt][2] * i1, oc[nt][3] * i1, H, L);
            base = A2 + (size_t)(r + 8) * 2304 + c;
            *(__nv_bfloat162*)base = H;
            *(__nv_bfloat162*)(base + 768) = L;
            *(__nv_bfloat162*)(base + 1536) = H;
        }
    }
}

// ---------------- launch ----------------
extern "C" void kernel_launch(void* const* d_in, const int* in_sizes, int n_in,
                              void* d_out, int out_size) {
    const float* x      = (const float*)d_in[0];
    const float* qkv_w  = (const float*)d_in[1];
    const float* qkv_b  = (const float*)d_in[2];
    const float* proj_w = (const float*)d_in[3];
    const float* proj_b = (const float*)d_in[4];
    float* out = (float*)d_out;

    __nv_bfloat16 *A2, *B1, *B2, *Q2, *K2, *V2;
    cudaGetSymbolAddress((void**)&A2,  g_A2);
    cudaGetSymbolAddress((void**)&B1,  g_B1);
    cudaGetSymbolAddress((void**)&B2,  g_B2);
    cudaGetSymbolAddress((void**)&Q2,  g_Q2);
    cudaGetSymbolAddress((void**)&K2,  g_K2);
    cudaGetSymbolAddress((void**)&V2,  g_V2);

    const int gemm_smem = 4 * 20480;  // 81920
    cudaFuncSetAttribute(mma_gemm, cudaFuncAttributeMaxDynamicSharedMemorySize, gemm_smem);
    cudaFuncSetAttribute(attn5, cudaFuncAttributeMaxDynamicSharedMemorySize, AT5_SMEM);

    split3<<<(4096 * 192 + 255) / 256, 256>>>(x, A2, 4096, 768, 1);
    split3<<<(2304 * 192 + 255) / 256, 256>>>(qkv_w, B1, 2304, 768, 0);

    // 1) qkv GEMM with fused per-head hi/lo split output
    mma_gemm<<<dim3(18, 32), 256, gemm_smem>>>(A2, B1, qkv_b, nullptr,
                                               Q2, K2, V2, 1, 4096, 2304, 2304);

    // 2) attention -> A2 ([hi|lo|hi] split, ready for proj GEMM)
    attn5<<<dim3(16, 24), 256, AT5_SMEM>>>(Q2, K2, V2, A2);

    split3<<<(768 * 192 + 255) / 256, 256>>>(proj_w, B2, 768, 768, 0);

    // 3) out = ao @ proj_w^T + proj_b
    mma_gemm<<<dim3(6, 32), 256, gemm_smem>>>(A2, B2, proj_b, out,
                                              nullptr, nullptr, nullptr, 0, 4096, 768, 2304);
}

// round 10
// speedup vs baseline: 2.5273x; 1.0130x over previous
#include <cuda_runtime.h>
#include <cuda_bf16.h>
#include <cstdint>

// ---------------- scratch (no cudaMalloc allowed) ----------------
__device__ __nv_bfloat16 g_A2[4096 * 2304];          // x-split, later ao-split [hi|lo|hi]
__device__ __nv_bfloat16 g_B1[2304 * 2304];          // qkv_w split [hi|hi|lo]
__device__ __nv_bfloat16 g_B2[768 * 2304];           // proj_w split [hi|hi|lo]
__device__ __nv_bfloat16 g_Q2[24 * 2048 * 128];      // per-head hi|lo (Q pre-scaled)
__device__ __nv_bfloat16 g_K2[24 * 2048 * 128];
__device__ __nv_bfloat16 g_V2[24 * 2048 * 128];

#define QSC 0.18033688f   // 0.125 * log2(e)

// ================= helpers =================
__device__ __forceinline__ uint32_t smem_u32(const void* p) {
    uint32_t a;
    asm("{ .reg .u64 t; cvta.to.shared.u64 t, %1; cvt.u32.u64 %0, t; }" : "=r"(a) : "l"(p));
    return a;
}
__device__ __forceinline__ void ldsm4(uint32_t* r, uint32_t a) {
    asm volatile("ldmatrix.sync.aligned.m8n8.x4.shared.b16 {%0,%1,%2,%3}, [%4];"
                 : "=r"(r[0]), "=r"(r[1]), "=r"(r[2]), "=r"(r[3]) : "r"(a));
}
__device__ __forceinline__ void ldsm4t(uint32_t* r, uint32_t a) {
    asm volatile("ldmatrix.sync.aligned.m8n8.x4.trans.shared.b16 {%0,%1,%2,%3}, [%4];"
                 : "=r"(r[0]), "=r"(r[1]), "=r"(r[2]), "=r"(r[3]) : "r"(a));
}
__device__ __forceinline__ void mma16816(float* d, const uint32_t* a, uint32_t b0, uint32_t b1) {
    asm volatile("mma.sync.aligned.m16n8k16.row.col.f32.bf16.bf16.f32 "
                 "{%0,%1,%2,%3},{%4,%5,%6,%7},{%8,%9},{%0,%1,%2,%3};"
                 : "+f"(d[0]), "+f"(d[1]), "+f"(d[2]), "+f"(d[3])
                 : "r"(a[0]), "r"(a[1]), "r"(a[2]), "r"(a[3]), "r"(b0), "r"(b1));
}
__device__ __forceinline__ void cp16(uint32_t saddr, const void* gaddr) {
    asm volatile("cp.async.cg.shared.global [%0], [%1], 16;" :: "r"(saddr), "l"(gaddr));
}
__device__ __forceinline__ void cp_commit() { asm volatile("cp.async.commit_group;" ::: "memory"); }
__device__ __forceinline__ void cp_wait2()  { asm volatile("cp.async.wait_group 2;" ::: "memory"); }
__device__ __forceinline__ void cp_wait1()  { asm volatile("cp.async.wait_group 1;" ::: "memory"); }
__device__ __forceinline__ void cp_wait0()  { asm volatile("cp.async.wait_group 0;" ::: "memory"); }

__device__ __forceinline__ void split2(float x, float y, __nv_bfloat162& hi, __nv_bfloat162& lo) {
    hi = __float22bfloat162_rn(make_float2(x, y));
    float2 b = __bfloat1622float2(hi);
    lo = __float22bfloat162_rn(make_float2(x - b.x, y - b.y));
}

// ===== split-concat: f32 -> [R][3K] bf16 (GEMM operands) =====
__global__ void split3(const float* __restrict__ in, __nv_bfloat16* __restrict__ out,
                       int R, int K, int loMid) {
    int i = blockIdx.x * blockDim.x + threadIdx.x;
    int per_row = K >> 2;
    if (i >= R * per_row) return;
    int r = i / per_row, f = i % per_row;
    float4 v = *(const float4*)(in + (size_t)r * K + f * 4);
    __nv_bfloat162 H0, H1, L0, L1;
    split2(v.x, v.y, H0, L0);
    split2(v.z, v.w, H1, L1);
    __nv_bfloat16* o = out + (size_t)r * 3 * K + f * 4;
    ((__nv_bfloat162*)o)[0] = H0;  ((__nv_bfloat162*)o)[1] = H1;
    if (loMid) {
        ((__nv_bfloat162*)(o + K))[0] = L0;     ((__nv_bfloat162*)(o + K))[1] = L1;
        ((__nv_bfloat162*)(o + 2 * K))[0] = H0; ((__nv_bfloat162*)(o + 2 * K))[1] = H1;
    } else {
        ((__nv_bfloat162*)(o + K))[0] = H0;     ((__nv_bfloat162*)(o + K))[1] = H1;
        ((__nv_bfloat162*)(o + 2 * K))[0] = L0; ((__nv_bfloat162*)(o + 2 * K))[1] = L1;
    }
}

// ================= bf16 GEMM, 4-stage; optional fused per-head split output ============
__global__ __launch_bounds__(256, 2)
void mma_gemm(const __nv_bfloat16* __restrict__ A, const __nv_bfloat16* __restrict__ B,
              const float* __restrict__ bias, float* __restrict__ C,
              __nv_bfloat16* __restrict__ Q2o, __nv_bfloat16* __restrict__ K2o,
              __nv_bfloat16* __restrict__ V2o, int splitOut,
              int M, int N, int K3) {
    extern __shared__ char sm[];
    const uint32_t sb = smem_u32(sm);
    const int tid = threadIdx.x, wid = tid >> 5, lane = tid & 31;
    const int wm = wid & 3, wn = wid >> 2;
    const int mBase = blockIdx.y * 128, nBase = blockIdx.x * 128;
    const int NIT = K3 / 32;

    float acc[2][8][4] = {};

    auto load_stage = [&](int st, int k0) {
        uint32_t sA = sb + st * 20480, sB = sA + 10240;
#pragma unroll
        for (int i2 = 0; i2 < 2; i2++) {
            int c = tid + i2 * 256;
            int row = c >> 2, kc = c & 3;
            cp16(sA + row * 80 + kc * 16, A + (size_t)(mBase + row) * K3 + k0 + kc * 8);
            cp16(sB + row * 80 + kc * 16, B + (size_t)(nBase + row) * K3 + k0 + kc * 8);
        }
    };

    load_stage(0, 0);  cp_commit();
    load_stage(1, 32); cp_commit();
    load_stage(2, 64); cp_commit();

    for (int it = 0; it < NIT; it++) {
        cp_wait2();
        __syncthreads();
        if (it + 3 < NIT) { load_stage((it + 3) & 3, (it + 3) * 32); }
        cp_commit();

        uint32_t sA = sb + (it & 3) * 20480, sB = sA + 10240;
#pragma unroll
        for (int kk = 0; kk < 2; kk++) {
            uint32_t a[2][4], bq[4][4];
#pragma unroll
            for (int mt = 0; mt < 2; mt++)
                ldsm4(a[mt], sA + (wm * 32 + mt * 16 + (lane & 15)) * 80 + kk * 32 + (lane >> 4) * 16);
#pragma unroll
            for (int p = 0; p < 4; p++)
                ldsm4(bq[p], sB + (wn * 64 + p * 16 + (lane & 15)) * 80 + kk * 32 + (lane >> 4) * 16);
#pragma unroll
            for (int mt = 0; mt < 2; mt++)
#pragma unroll
                for (int nt = 0; nt < 8; nt++) {
                    int p = nt >> 1, j = nt & 1;
                    mma16816(acc[mt][nt], a[mt], bq[p][j], bq[p][j + 2]);
                }
        }
    }

    const int cbase = nBase + wn * 64;
#pragma unroll
    for (int nt = 0; nt < 8; nt++) {
        int col = cbase + nt * 8 + 2 * (lane & 3);
        float2 bv = *(const float2*)(bias + col);
#pragma unroll
        for (int mt = 0; mt < 2; mt++) {
            int r0 = mBase + wm * 32 + mt * 16 + (lane >> 2);
            float2 v0; v0.x = acc[mt][nt][0] + bv.x; v0.y = acc[mt][nt][1] + bv.y;
            float2 v1; v1.x = acc[mt][nt][2] + bv.x; v1.y = acc[mt][nt][3] + bv.y;
            if (!splitOut) {
                *(float2*)(C + (size_t)r0 * N + col) = v0;
                *(float2*)(C + (size_t)(r0 + 8) * N + col) = v1;
            } else {
                int m = col / 768;
                int hc = col - m * 768;
                int h = hc >> 6, d = hc & 63;
                __nv_bfloat16* base = (m == 0 ? Q2o : m == 1 ? K2o : V2o);
                float qs = (m == 0) ? QSC : 1.0f;   // fold softmax scale*log2e into Q
                __nv_bfloat162 H, L;
#pragma unroll
                for (int rr = 0; rr < 2; rr++) {
                    int r = r0 + rr * 8;
                    float2 v = rr ? v1 : v0;
                    split2(v.x * qs, v.y * qs, H, L);
                    __nv_bfloat16* dst = base +
                        ((size_t)((r >> 11) * 12 + h) * 2048 + (r & 2047)) * 128 + d;
                    *(__nv_bfloat162*)dst = H;
                    *(__nv_bfloat162*)(dst + 64) = L;
                }
            }
        }
    }
}

// ================= flash attention v6: pipelined S, exp2 softmax, 3-stage KV ring =======
// Smem: Q[128][272B]@0 (34816) ; 3 KV stages of (K 32x272=8704, V 64x144=9216) = 17920 each.
#define AT6_SMEM (34816 + 3 * 17920)   // 88576

__device__ __forceinline__ void computeS(float (&sc)[4][4], uint32_t Qu, uint32_t Kst,
                                         int wid, int lane) {
#pragma unroll
    for (int nt = 0; nt < 4; nt++)
#pragma unroll
        for (int j = 0; j < 4; j++) sc[nt][j] = 0.f;
#pragma unroll
    for (int g = 0; g < 4; g++) {
        const uint32_t qrow = Qu + (wid * 16 + (lane & 15)) * 272 + g * 32 + (lane >> 4) * 16;
        const uint32_t krow0 = Kst + (lane & 15) * 272 + g * 32 + (lane >> 4) * 16;
        const uint32_t krow1 = Kst + (16 + (lane & 15)) * 272 + g * 32 + (lane >> 4) * 16;
        uint32_t aqh[4], aql[4], bh0[4], bh1[4], bl0[4], bl1[4];
        ldsm4(aqh, qrow);
        ldsm4(aql, qrow + 128);
        ldsm4(bh0, krow0);
        ldsm4(bh1, krow1);
        ldsm4(bl0, krow0 + 128);
        ldsm4(bl1, krow1 + 128);
        mma16816(sc[0], aqh, bh0[0], bh0[2]); mma16816(sc[1], aqh, bh0[1], bh0[3]);
        mma16816(sc[2], aqh, bh1[0], bh1[2]); mma16816(sc[3], aqh, bh1[1], bh1[3]);
        mma16816(sc[0], aql, bh0[0], bh0[2]); mma16816(sc[1], aql, bh0[1], bh0[3]);
        mma16816(sc[2], aql, bh1[0], bh1[2]); mma16816(sc[3], aql, bh1[1], bh1[3]);
        mma16816(sc[0], aqh, bl0[0], bl0[2]); mma16816(sc[1], aqh, bl0[1], bl0[3]);
        mma16816(sc[2], aqh, bl1[0], bl1[2]); mma16816(sc[3], aqh, bl1[1], bl1[3]);
    }
}

__global__ __launch_bounds__(256, 2)
void attn6(const __nv_bfloat16* __restrict__ Q2, const __nv_bfloat16* __restrict__ K2,
           const __nv_bfloat16* __restrict__ V2, __nv_bfloat16* __restrict__ A2) {
    extern __shared__ char sm[];
    const uint32_t sb = smem_u32(sm);
    const uint32_t Qu = sb;

    const int tid = threadIdx.x, wid = tid >> 5, lane = tid & 31;
    const int bh = blockIdx.y;
    const int q0 = blockIdx.x * 128;

    const __nv_bfloat16* Qg = Q2 + ((size_t)bh * 2048 + q0) * 128;
    const __nv_bfloat16* Kg0 = K2 + (size_t)bh * 2048 * 128;
    const __nv_bfloat16* Vg0 = V2 + (size_t)bh * 2048 * 128;

    auto stageK = [&](int st) { return sb + 34816 + st * 17920; };

    auto loadKV = [&](int st, int kt) {
        const __nv_bfloat16* Kg = Kg0 + (size_t)kt * 32 * 128;
        const __nv_bfloat16* Vg = Vg0 + (size_t)kt * 32 * 128;
        uint32_t Ku = stageK(st), Vu = Ku + 8704;
#pragma unroll
        for (int i = 0; i < 2; i++) {
            int idx = tid + i * 256;
            int row = idx >> 4, j = idx & 15;
            cp16(Ku + row * 272 + j * 16, Kg + row * 128 + j * 8);
        }
#pragma unroll
        for (int i = 0; i < 2; i++) {
            int idx = tid + i * 256;
            int row = idx >> 3, j = idx & 7;
            cp16(Vu + row * 144 + j * 16,
                 Vg + (row & 31) * 128 + (row >> 5) * 64 + j * 8);
        }
    };

    // prologue: Q + KV0 (group0), KV1 (group1)
#pragma unroll
    for (int i = 0; i < 8; i++) {
        int idx = tid + i * 256;
        int row = idx >> 4, j = idx & 15;
        cp16(Qu + row * 272 + j * 16, Qg + row * 128 + j * 8);
    }
    loadKV(0, 0);
    cp_commit();
    loadKV(1, 1);
    cp_commit();
    cp_wait1();
    __syncthreads();

    float oc[8][4] = {};
    float mrow[2] = { -1e30f, -1e30f };
    float lrow[2] = { 0.f, 0.f };
    float sc0[4][4], sc1[4][4];

    computeS(sc0, Qu, stageK(0), wid, lane);

    auto body = [&](float (&scCur)[4][4], float (&scNxt)[4][4], int kt) {
        __syncthreads();                       // prior iter's V reads done
        if (kt + 2 < 64) {
            loadKV((kt + 2) % 3, kt + 2);
            cp_commit();
            cp_wait1();                        // KV(kt+1) complete
        } else {
            cp_wait0();
        }
        __syncthreads();                       // KV(kt+1) visible

        if (kt + 1 < 64)
            computeS(scNxt, Qu, stageK((kt + 1) % 3), wid, lane);

        // ---- softmax(kt) on scCur (values pre-scaled by QSC; base-2 domain) ----
        float m0 = -1e30f, m1 = -1e30f;
#pragma unroll
        for (int nt = 0; nt < 4; nt++) {
            m0 = fmaxf(m0, fmaxf(scCur[nt][0], scCur[nt][1]));
            m1 = fmaxf(m1, fmaxf(scCur[nt][2], scCur[nt][3]));
        }
        m0 = fmaxf(m0, __shfl_xor_sync(0xffffffffu, m0, 1));
        m0 = fmaxf(m0, __shfl_xor_sync(0xffffffffu, m0, 2));
        m1 = fmaxf(m1, __shfl_xor_sync(0xffffffffu, m1, 1));
        m1 = fmaxf(m1, __shfl_xor_sync(0xffffffffu, m1, 2));
        float mn0 = fmaxf(mrow[0], m0), mn1 = fmaxf(mrow[1], m1);
        float al0 = exp2f(mrow[0] - mn0), al1 = exp2f(mrow[1] - mn1);
        mrow[0] = mn0; mrow[1] = mn1;

        float s0 = 0.f, s1 = 0.f;
#pragma unroll
        for (int nt = 0; nt < 4; nt++) {
            scCur[nt][0] = exp2f(scCur[nt][0] - mn0);
            scCur[nt][1] = exp2f(scCur[nt][1] - mn0);
            scCur[nt][2] = exp2f(scCur[nt][2] - mn1);
            scCur[nt][3] = exp2f(scCur[nt][3] - mn1);
            s0 += scCur[nt][0] + scCur[nt][1];
            s1 += scCur[nt][2] + scCur[nt][3];
        }
        s0 += __shfl_xor_sync(0xffffffffu, s0, 1);
        s0 += __shfl_xor_sync(0xffffffffu, s0, 2);
        s1 += __shfl_xor_sync(0xffffffffu, s1, 1);
        s1 += __shfl_xor_sync(0xffffffffu, s1, 2);
        lrow[0] = lrow[0] * al0 + s0;
        lrow[1] = lrow[1] * al1 + s1;

#pragma unroll
        for (int nt = 0; nt < 8; nt++) {
            oc[nt][0] *= al0; oc[nt][1] *= al0;
            oc[nt][2] *= al1; oc[nt][3] *= al1;
        }

        // ---- PV(kt): kg outer (pack once), vt inner ----
        const uint32_t Vst = stageK(kt % 3) + 8704;
#pragma unroll
        for (int kg = 0; kg < 2; kg++) {
            uint32_t Ph[4], Pl[4];
#pragma unroll
            for (int e = 0; e < 2; e++) {
                const float* f0 = scCur[kg * 2];
                const float* f1 = scCur[kg * 2 + 1];
                __nv_bfloat162 H, L;
                split2(f0[e * 2], f0[e * 2 + 1], H, L);
                Ph[e] = *(uint32_t*)&H; Pl[e] = *(uint32_t*)&L;
                split2(f1[e * 2], f1[e * 2 + 1], H, L);
                Ph[e + 2] = *(uint32_t*)&H; Pl[e + 2] = *(uint32_t*)&L;
            }
#pragma unroll
            for (int vt = 0; vt < 2; vt++) {
                uint32_t bv[4][4];
#pragma unroll
                for (int p = 0; p < 4; p++)
                    ldsm4t(bv[p], Vst + (vt * 32 + kg * 16 + (lane & 15)) * 144 +
                                   p * 32 + (lane >> 4) * 16);
#pragma unroll
                for (int p = 0; p < 4; p++)
#pragma unroll
                    for (int j = 0; j < 2; j++) {
                        mma16816(oc[p * 2 + j], Ph, bv[p][j * 2], bv[p][j * 2 + 1]);
                        if (vt == 0)
                            mma16816(oc[p * 2 + j], Pl, bv[p][j * 2], bv[p][j * 2 + 1]);
                    }
            }
        }
    };

    for (int kt = 0; kt < 64; kt += 2) {
        body(sc0, sc1, kt);
        body(sc1, sc0, kt + 1);
    }

    // ---- epilogue: write split [hi|lo|hi] rows of A2 ----
    {
        int b = bh / 12, h = bh % 12;
        float i0 = 1.0f / lrow[0], i1 = 1.0f / lrow[1];
        int r = b * 2048 + q0 + wid * 16 + (lane >> 2);
#pragma unroll
        for (int nt = 0; nt < 8; nt++) {
            int c = h * 64 + nt * 8 + 2 * (lane & 3);
            __nv_bfloat162 H, L;
            split2(oc[nt][0] * i0, oc[nt][1] * i0, H, L);
            __nv_bfloat16* base = A2 + (size_t)r * 2304 + c;
            *(__nv_bfloat162*)base = H;
            *(__nv_bfloat162*)(base + 768) = L;
            *(__nv_bfloat162*)(base + 1536) = H;
            split2(oc[nt][2] * i1, oc[nt][3] * i1, H, L);
            base = A2 + (size_t)(r + 8) * 2304 + c;
            *(__nv_bfloat162*)base = H;
            *(__nv_bfloat162*)(base + 768) = L;
            *(__nv_bfloat162*)(base + 1536) = H;
        }
    }
}

// ---------------- launch ----------------
extern "C" void kernel_launch(void* const* d_in, const int* in_sizes, int n_in,
                              void* d_out, int out_size) {
    const float* x      = (const float*)d_in[0];
    const float* qkv_w  = (const float*)d_in[1];
    const float* qkv_b  = (const float*)d_in[2];
    const float* proj_w = (const float*)d_in[3];
    const float* proj_b = (const float*)d_in[4];
    float* out = (float*)d_out;

    __nv_bfloat16 *A2, *B1, *B2, *Q2, *K2, *V2;
    cudaGetSymbolAddress((void**)&A2,  g_A2);
    cudaGetSymbolAddress((void**)&B1,  g_B1);
    cudaGetSymbolAddress((void**)&B2,  g_B2);
    cudaGetSymbolAddress((void**)&Q2,  g_Q2);
    cudaGetSymbolAddress((void**)&K2,  g_K2);
    cudaGetSymbolAddress((void**)&V2,  g_V2);

    const int gemm_smem = 4 * 20480;
    cudaFuncSetAttribute(mma_gemm, cudaFuncAttributeMaxDynamicSharedMemorySize, gemm_smem);
    cudaFuncSetAttribute(attn6, cudaFuncAttributeMaxDynamicSharedMemorySize, AT6_SMEM);

    split3<<<(4096 * 192 + 255) / 256, 256>>>(x, A2, 4096, 768, 1);
    split3<<<(2304 * 192 + 255) / 256, 256>>>(qkv_w, B1, 2304, 768, 0);

    // 1) qkv GEMM with fused per-head hi/lo split output (Q pre-scaled by QSC)
    mma_gemm<<<dim3(18, 32), 256, gemm_smem>>>(A2, B1, qkv_b, nullptr,
                                               Q2, K2, V2, 1, 4096, 2304, 2304);

    // 2) attention -> A2 ([hi|lo|hi] split, ready for proj GEMM)
    attn6<<<dim3(16, 24), 256, AT6_SMEM>>>(Q2, K2, V2, A2);

    split3<<<(768 * 192 + 255) / 256, 256>>>(proj_w, B2, 768, 768, 0);

    // 3) out = ao @ proj_w^T + proj_b
    mma_gemm<<<dim3(6, 32), 256, gemm_smem>>>(A2, B2, proj_b, out,
                                              nullptr, nullptr, nullptr, 0, 4096, 768, 2304);
}